// round 12
// baseline (speedup 1.0000x reference)
#include <cuda_runtime.h>
#include <cuda_bf16.h>
#include <cstdint>
#include <math.h>

#define S_LEN    4096
#define D_MODEL  1024
#define QKV_COLS 3072
#define N_HEADS  16
#define HEAD_DIM 64
#define ATT_SCALE 0.125f

// ---------------- scratch (__device__ globals; no cudaMalloc) ----------------
static __device__ __align__(256) __nv_bfloat16 g_xh[S_LEN * D_MODEL];
static __device__ __align__(256) __nv_bfloat16 g_xl[S_LEN * D_MODEL];
static __device__ __align__(256) __nv_bfloat16 g_qh[S_LEN * QKV_COLS];
static __device__ __align__(256) __nv_bfloat16 g_ql[S_LEN * QKV_COLS];
static __device__ __align__(256) __nv_bfloat16 g_ah[S_LEN * D_MODEL];
static __device__ __align__(256) __nv_bfloat16 g_al[S_LEN * D_MODEL];
static __device__ __align__(256) __nv_bfloat16 g_wqh[QKV_COLS * D_MODEL]; // [N][K]
static __device__ __align__(256) __nv_bfloat16 g_wql[QKV_COLS * D_MODEL];
static __device__ __align__(256) __nv_bfloat16 g_woh[D_MODEL * D_MODEL];
static __device__ __align__(256) __nv_bfloat16 g_wol[D_MODEL * D_MODEL];

// ---------------- PTX helpers ----------------
__device__ __forceinline__ uint32_t smem_u32(const void* p) {
    uint32_t a;
    asm("{ .reg .u64 t; cvta.to.shared.u64 t, %1; cvt.u32.u64 %0, t; }"
        : "=r"(a) : "l"(p));
    return a;
}
__device__ __forceinline__ void cp_async16(uint32_t saddr, const void* gptr) {
    asm volatile("cp.async.cg.shared.global [%0], [%1], 16;"
                 :: "r"(saddr), "l"(gptr));
}
#define CP_COMMIT() asm volatile("cp.async.commit_group;" ::: "memory")
#define CP_WAIT(n)  asm volatile("cp.async.wait_group %0;" :: "n"(n) : "memory")

__device__ __forceinline__ void ldsm_x4(uint32_t* r, uint32_t addr) {
    asm volatile("ldmatrix.sync.aligned.m8n8.x4.shared.b16 {%0,%1,%2,%3}, [%4];"
                 : "=r"(r[0]), "=r"(r[1]), "=r"(r[2]), "=r"(r[3]) : "r"(addr));
}
__device__ __forceinline__ void ldsm_x4_t(uint32_t* r, uint32_t addr) {
    asm volatile("ldmatrix.sync.aligned.m8n8.x4.trans.shared.b16 {%0,%1,%2,%3}, [%4];"
                 : "=r"(r[0]), "=r"(r[1]), "=r"(r[2]), "=r"(r[3]) : "r"(addr));
}
__device__ __forceinline__ void mma_bf16(float* c, const uint32_t* a, const uint32_t* b) {
    asm volatile("mma.sync.aligned.m16n8k16.row.col.f32.bf16.bf16.f32 "
                 "{%0,%1,%2,%3}, {%4,%5,%6,%7}, {%8,%9}, {%0,%1,%2,%3};"
                 : "+f"(c[0]), "+f"(c[1]), "+f"(c[2]), "+f"(c[3])
                 : "r"(a[0]), "r"(a[1]), "r"(a[2]), "r"(a[3]), "r"(b[0]), "r"(b[1]));
}
__device__ __forceinline__ void split_pack(float x, float y, uint32_t& hi, uint32_t& lo) {
    __nv_bfloat16 hx = __float2bfloat16(x), hy = __float2bfloat16(y);
    __nv_bfloat16 lx = __float2bfloat16(x - __bfloat162float(hx));
    __nv_bfloat16 ly = __float2bfloat16(y - __bfloat162float(hy));
    hi = ((uint32_t)__bfloat16_as_ushort(hy) << 16) | __bfloat16_as_ushort(hx);
    lo = ((uint32_t)__bfloat16_as_ushort(ly) << 16) | __bfloat16_as_ushort(lx);
}

// ---------------- convert kernels ----------------
__global__ void split_rows_kernel(const float* __restrict__ src,
                                  __nv_bfloat16* __restrict__ hi,
                                  __nv_bfloat16* __restrict__ lo, int n)
{
    int i = (blockIdx.x * blockDim.x + threadIdx.x) * 4;
    if (i >= n) return;
    float4 v = *(const float4*)(src + i);
    __nv_bfloat16 h0 = __float2bfloat16(v.x), h1 = __float2bfloat16(v.y);
    __nv_bfloat16 h2 = __float2bfloat16(v.z), h3 = __float2bfloat16(v.w);
    hi[i] = h0; hi[i+1] = h1; hi[i+2] = h2; hi[i+3] = h3;
    lo[i]   = __float2bfloat16(v.x - __bfloat162float(h0));
    lo[i+1] = __float2bfloat16(v.y - __bfloat162float(h1));
    lo[i+2] = __float2bfloat16(v.z - __bfloat162float(h2));
    lo[i+3] = __float2bfloat16(v.w - __bfloat162float(h3));
}

__global__ void transpose_split_kernel(const float* __restrict__ w,
                                       __nv_bfloat16* __restrict__ hi,
                                       __nv_bfloat16* __restrict__ lo,
                                       int K, int N)
{
    __shared__ float tile[32][33];
    const int n0 = blockIdx.x * 32, k0 = blockIdx.y * 32;
    const int tx = threadIdx.x, ty = threadIdx.y;   // 32 x 8
#pragma unroll
    for (int i = 0; i < 4; i++)
        tile[ty + 8 * i][tx] = w[(size_t)(k0 + ty + 8 * i) * N + n0 + tx];
    __syncthreads();
#pragma unroll
    for (int i = 0; i < 4; i++) {
        const int r = ty + 8 * i;
        float v = tile[tx][r];
        __nv_bfloat16 h = __float2bfloat16(v);
        hi[(size_t)(n0 + r) * K + k0 + tx] = h;
        lo[(size_t)(n0 + r) * K + k0 + tx] =
            __float2bfloat16(v - __bfloat162float(h));
    }
}

// ---------------- raw mma.sync bf16 hi/lo GEMM, BK=64, 2-stage, 1 CTA/SM ----
// Per-barrier work matched to the flash-attention kernel (192 HMMA/warp).
#define GLD 72                            // smem row stride (elems): 64 data + 8 pad
#define GTILE  (128 * GLD * 2)            // 18432 B per array
#define GSTAGE (4 * GTILE)                // 73728 B per stage
#define GEMM_SMEM (2 * GSTAGE)            // 147456 B (epilogue 67584 B aliases)

__global__ __launch_bounds__(256, 1)
void gemm_mma_kernel(const __nv_bfloat16* __restrict__ Ah,
                     const __nv_bfloat16* __restrict__ Al,
                     const __nv_bfloat16* __restrict__ Bh,
                     const __nv_bfloat16* __restrict__ Bl,
                     const float* __restrict__ bias,
                     float* __restrict__ Cf,
                     __nv_bfloat16* __restrict__ Ch,
                     __nv_bfloat16* __restrict__ Cl,
                     int hilo, int M, int N, int K)
{
    extern __shared__ char smraw[];
    float* Cs = (float*)smraw;
    const uint32_t sb = smem_u32(smraw);

    const int tid = threadIdx.x;
    const int wid = tid >> 5;
    const int lane = tid & 31;
    const int wr = wid >> 1;          // 0..3 -> m rows wr*32
    const int wc = wid & 1;           // 0..1 -> n cols wc*64
    const int g  = lane >> 2;
    const int t  = lane & 3;
    const int lr = lane & 15;
    const int lc8 = (lane >> 4) * 8;
    const int kk = (lane & 7) + ((lane & 16) >> 1);
    const int kd8 = lane & 8;
    const int m0 = blockIdx.y * 128, n0 = blockIdx.x * 128;

    float acc[16][4];
#pragma unroll
    for (int q = 0; q < 16; q++)
#pragma unroll
        for (int e = 0; e < 4; e++) acc[q][e] = 0.f;

    // cp.async coords: per array, 4 chunks per thread (128 rows x 8 x 16B)
    int crow[4], cbyte[4];
#pragma unroll
    for (int i = 0; i < 4; i++) {
        const int idx = tid + i * 256;     // 0..1023
        crow[i]  = idx >> 3;               // 0..127
        cbyte[i] = (idx & 7) * 16;         // 0..112 bytes within k-tile
    }
    const __nv_bfloat16* pA[2] = { Ah, Al };
    const __nv_bfloat16* pB[2] = { Bh, Bl };

    const int NT = K / 64;

    // prefetch stage 0
#pragma unroll
    for (int i = 0; i < 4; i++) {
        const int r = crow[i];
        const int gcol = cbyte[i] / 2;
        const uint32_t so = (uint32_t)(r * GLD * 2 + cbyte[i]);
        cp_async16(sb + so,             pA[0] + (size_t)(m0 + r) * K + gcol);
        cp_async16(sb + GTILE + so,     pA[1] + (size_t)(m0 + r) * K + gcol);
        cp_async16(sb + 2 * GTILE + so, pB[0] + (size_t)(n0 + r) * K + gcol);
        cp_async16(sb + 3 * GTILE + so, pB[1] + (size_t)(n0 + r) * K + gcol);
    }
    CP_COMMIT();

    for (int kt = 0; kt < NT; kt++) {
        __syncthreads();   // next-stage buffer free
        if (kt + 1 < NT) {
            const int k1 = (kt + 1) * 64;
            const uint32_t st = sb + ((kt + 1) & 1) * GSTAGE;
#pragma unroll
            for (int i = 0; i < 4; i++) {
                const int r = crow[i];
                const int gcol = k1 + cbyte[i] / 2;
                const uint32_t so = (uint32_t)(r * GLD * 2 + cbyte[i]);
                cp_async16(st + so,             pA[0] + (size_t)(m0 + r) * K + gcol);
                cp_async16(st + GTILE + so,     pA[1] + (size_t)(m0 + r) * K + gcol);
                cp_async16(st + 2 * GTILE + so, pB[0] + (size_t)(n0 + r) * K + gcol);
                cp_async16(st + 3 * GTILE + so, pB[1] + (size_t)(n0 + r) * K + gcol);
            }
            CP_COMMIT();
            CP_WAIT(1);
        } else {
            CP_WAIT(0);
        }
        __syncthreads();   // stage kt visible

        const uint32_t uAh = sb + (kt & 1) * GSTAGE;
        const uint32_t uAl = uAh + GTILE;
        const uint32_t uBh = uAh + 2 * GTILE;
        const uint32_t uBl = uAh + 3 * GTILE;

#pragma unroll
        for (int u = 0; u < 4; u++) {            // k16 step within stage
            uint32_t ah[2][4], al[2][4];
#pragma unroll
            for (int i = 0; i < 2; i++) {
                const uint32_t aoff =
                    (uint32_t)(((wr * 32 + i * 16 + lr) * GLD + u * 16 + lc8) * 2);
                ldsm_x4(ah[i], uAh + aoff);
                ldsm_x4(al[i], uAl + aoff);
            }
#pragma unroll
            for (int jj = 0; jj < 4; jj++) {     // n16 block
                uint32_t bh[4], bl[4];
                const uint32_t boff =
                    (uint32_t)(((wc * 64 + jj * 16 + kk) * GLD + u * 16 + kd8) * 2);
                ldsm_x4(bh, uBh + boff);
                ldsm_x4(bl, uBl + boff);
#pragma unroll
                for (int i = 0; i < 2; i++) {
                    float* c0 = acc[i * 8 + 2 * jj];
                    float* c1 = acc[i * 8 + 2 * jj + 1];
                    mma_bf16(c0, ah[i], bh);
                    mma_bf16(c0, ah[i], bl);
                    mma_bf16(c0, al[i], bh);
                    mma_bf16(c1, ah[i], bh + 2);
                    mma_bf16(c1, ah[i], bl + 2);
                    mma_bf16(c1, al[i], bh + 2);
                }
            }
        }
    }

    __syncthreads();   // all ldsm done before Cs overwrites stage smem
#pragma unroll
    for (int i = 0; i < 2; i++)
#pragma unroll
        for (int f = 0; f < 8; f++) {
            const int row = wr * 32 + i * 16 + g;
            const int col = wc * 64 + 8 * f + 2 * t;
            const float* c = acc[i * 8 + f];
            *(float2*)&Cs[row * 132 + col]       = make_float2(c[0], c[1]);
            *(float2*)&Cs[(row + 8) * 132 + col] = make_float2(c[2], c[3]);
        }
    __syncthreads();

    {
        const int r = tid >> 1;
        const int cb = (tid & 1) * 64;
        const float* bp = bias + n0 + cb;
        const float* sp = &Cs[r * 132 + cb];
        if (!hilo) {
            float* cp = Cf + (size_t)(m0 + r) * N + n0 + cb;
#pragma unroll
            for (int j = 0; j < 64; j += 4) {
                float4 o;
                o.x = sp[j+0] + bp[j+0]; o.y = sp[j+1] + bp[j+1];
                o.z = sp[j+2] + bp[j+2]; o.w = sp[j+3] + bp[j+3];
                *(float4*)(cp + j) = o;
            }
        } else {
            __nv_bfloat16* hp = Ch + (size_t)(m0 + r) * N + n0 + cb;
            __nv_bfloat16* lp = Cl + (size_t)(m0 + r) * N + n0 + cb;
#pragma unroll
            for (int j = 0; j < 64; j += 4) {
                uint32_t h0, l0, h1, l1;
                split_pack(sp[j+0] + bp[j+0], sp[j+1] + bp[j+1], h0, l0);
                split_pack(sp[j+2] + bp[j+2], sp[j+3] + bp[j+3], h1, l1);
                *(uint2*)(hp + j) = make_uint2(h0, h1);
                *(uint2*)(lp + j) = make_uint2(l0, l1);
            }
        }
    }
}

// ---------------------------------------------------------------------------
// Flash attention on mma.sync bf16 (hi/lo), cp.async double-buffered K/V.
// (identical to R8/R10/R11 version)
// ---------------------------------------------------------------------------
#define ALD 72                              // bf16 elems per smem row
#define FARR (128 * ALD * 2)                // 18432 B per array
#define FA_KVSTAGE (4 * FARR)               // Kh Kl Vh Vl = 73728 B
#define FA_KVBASE  (2 * FARR)               // after Qh Ql
#define FA_SMEM (FA_KVBASE + 2 * FA_KVSTAGE)  // 184320 B

__global__ __launch_bounds__(256, 1)
void flash_attn_mma_kernel(const __nv_bfloat16* __restrict__ qh,
                           const __nv_bfloat16* __restrict__ ql,
                           __nv_bfloat16* __restrict__ oh,
                           __nv_bfloat16* __restrict__ ol)
{
    extern __shared__ char smraw[];
    __nv_bfloat16* sQh = (__nv_bfloat16*)smraw;
    __nv_bfloat16* sQl = sQh + 128 * ALD;
    const uint32_t sb = smem_u32(smraw);

    const int qb  = gridDim.x - 1 - blockIdx.x;   // long rows first
    const int h   = blockIdx.y;
    const int tid = threadIdx.x;
    const int wid = tid >> 5;
    const int lane = tid & 31;
    const int q0  = qb * 128;

    const int g  = lane >> 2;
    const int t  = lane & 3;
    const int lr = lane & 15;
    const int lc8 = (lane >> 4) * 8;
    const int kk = (lane & 7) + ((lane & 16) >> 1);
    const int kd8 = lane & 8;

    const int colK = D_MODEL + h * HEAD_DIM;
    const int colV = 2 * D_MODEL + h * HEAD_DIM;

    int crow[4], cbyte[4];
#pragma unroll
    for (int i = 0; i < 4; i++) {
        const int idx = tid + i * 256;
        crow[i]  = idx >> 3;
        cbyte[i] = (idx & 7) * 16;
    }

    // ---- load Q tile ----
#pragma unroll
    for (int i = 0; i < 4; i++) {
        const int r = crow[i], c = cbyte[i] / 2;
        const size_t gofs = (size_t)(q0 + r) * QKV_COLS + h * HEAD_DIM + c;
        *(uint4*)(sQh + r * ALD + c) = *(const uint4*)(qh + gofs);
        *(uint4*)(sQl + r * ALD + c) = *(const uint4*)(ql + gofs);
    }

    // ---- prefetch K/V stage 0 ----
    {
        const uint32_t st = sb + FA_KVBASE;
#pragma unroll
        for (int i = 0; i < 4; i++) {
            const int r = crow[i];
            const uint32_t so = (uint32_t)(r * ALD * 2 + cbyte[i]);
            const size_t gr = (size_t)r * QKV_COLS;
            const int c = cbyte[i] / 2;
            cp_async16(st + so,            qh + gr + colK + c);
            cp_async16(st + FARR + so,     ql + gr + colK + c);
            cp_async16(st + 2 * FARR + so, qh + gr + colV + c);
            cp_async16(st + 3 * FARR + so, ql + gr + colV + c);
        }
        CP_COMMIT();
    }

    float ofr[8][4];
    float m0 = -1e30f, m1 = -1e30f, l0 = 0.f, l1 = 0.f;
#pragma unroll
    for (int j = 0; j < 8; j++)
#pragma unroll
        for (int e = 0; e < 4; e++) ofr[j][e] = 0.f;

    for (int kt = 0; kt <= qb; kt++) {
        __syncthreads();
        if (kt + 1 <= qb) {
            const int k1 = (kt + 1) * 128;
            const uint32_t st = sb + FA_KVBASE + ((kt + 1) & 1) * FA_KVSTAGE;
#pragma unroll
            for (int i = 0; i < 4; i++) {
                const int r = crow[i];
                const uint32_t so = (uint32_t)(r * ALD * 2 + cbyte[i]);
                const size_t gr = (size_t)(k1 + r) * QKV_COLS;
                const int c = cbyte[i] / 2;
                cp_async16(st + so,            qh + gr + colK + c);
                cp_async16(st + FARR + so,     ql + gr + colK + c);
                cp_async16(st + 2 * FARR + so, qh + gr + colV + c);
                cp_async16(st + 3 * FARR + so, ql + gr + colV + c);
            }
            CP_COMMIT();
            CP_WAIT(1);
        } else {
            CP_WAIT(0);
        }
        __syncthreads();

        const uint32_t stg = sb + FA_KVBASE + (kt & 1) * FA_KVSTAGE;
        const uint32_t uKh = stg, uKl = stg + FARR;
        const uint32_t uVh = stg + 2 * FARR, uVl = stg + 3 * FARR;
        const uint32_t uQh = sb, uQl = sb + FARR;

        float sfr[16][4];
#pragma unroll
        for (int j = 0; j < 16; j++)
#pragma unroll
            for (int e = 0; e < 4; e++) sfr[j][e] = 0.f;

#pragma unroll
        for (int u = 0; u < 4; u++) {
            uint32_t aQh[4], aQl[4];
            const uint32_t qoff =
                (uint32_t)(((wid * 16 + lr) * ALD + 16 * u + lc8) * 2);
            ldsm_x4(aQh, uQh + qoff);
            ldsm_x4(aQl, uQl + qoff);
#pragma unroll
            for (int jj = 0; jj < 8; jj++) {
                uint32_t bKh[4], bKl[4];
                const uint32_t koff =
                    (uint32_t)(((16 * jj + kk) * ALD + 16 * u + kd8) * 2);
                ldsm_x4(bKh, uKh + koff);
                ldsm_x4(bKl, uKl + koff);
                mma_bf16(sfr[2*jj],   aQh, bKh);
                mma_bf16(sfr[2*jj+1], aQh, bKh + 2);
                mma_bf16(sfr[2*jj],   aQh, bKl);
                mma_bf16(sfr[2*jj+1], aQh, bKl + 2);
                mma_bf16(sfr[2*jj],   aQl, bKh);
                mma_bf16(sfr[2*jj+1], aQl, bKh + 2);
            }
        }

        if (kt == qb) {
            const int gq0 = wid * 16 + g, gq1 = gq0 + 8;
#pragma unroll
            for (int j = 0; j < 16; j++) {
                const int c = 8 * j + 2 * t;
                sfr[j][0] = (c     <= gq0) ? sfr[j][0] * ATT_SCALE : -1e30f;
                sfr[j][1] = (c + 1 <= gq0) ? sfr[j][1] * ATT_SCALE : -1e30f;
                sfr[j][2] = (c     <= gq1) ? sfr[j][2] * ATT_SCALE : -1e30f;
                sfr[j][3] = (c + 1 <= gq1) ? sfr[j][3] * ATT_SCALE : -1e30f;
            }
        } else {
#pragma unroll
            for (int j = 0; j < 16; j++) {
                sfr[j][0] *= ATT_SCALE; sfr[j][1] *= ATT_SCALE;
                sfr[j][2] *= ATT_SCALE; sfr[j][3] *= ATT_SCALE;
            }
        }

        float mn0 = m0, mn1 = m1;
#pragma unroll
        for (int j = 0; j < 16; j++) {
            mn0 = fmaxf(mn0, fmaxf(sfr[j][0], sfr[j][1]));
            mn1 = fmaxf(mn1, fmaxf(sfr[j][2], sfr[j][3]));
        }
        mn0 = fmaxf(mn0, __shfl_xor_sync(0xffffffffu, mn0, 1));
        mn0 = fmaxf(mn0, __shfl_xor_sync(0xffffffffu, mn0, 2));
        mn1 = fmaxf(mn1, __shfl_xor_sync(0xffffffffu, mn1, 1));
        mn1 = fmaxf(mn1, __shfl_xor_sync(0xffffffffu, mn1, 2));

        const float alpha0 = __expf(m0 - mn0);
        const float alpha1 = __expf(m1 - mn1);
        m0 = mn0; m1 = mn1;

        float sum0 = 0.f, sum1 = 0.f;
#pragma unroll
        for (int j = 0; j < 16; j++) {
            sfr[j][0] = __expf(sfr[j][0] - mn0);
            sfr[j][1] = __expf(sfr[j][1] - mn0);
            sfr[j][2] = __expf(sfr[j][2] - mn1);
            sfr[j][3] = __expf(sfr[j][3] - mn1);
            sum0 += sfr[j][0] + sfr[j][1];
            sum1 += sfr[j][2] + sfr[j][3];
        }
        sum0 += __shfl_xor_sync(0xffffffffu, sum0, 1);
        sum0 += __shfl_xor_sync(0xffffffffu, sum0, 2);
        sum1 += __shfl_xor_sync(0xffffffffu, sum1, 1);
        sum1 += __shfl_xor_sync(0xffffffffu, sum1, 2);
        l0 = l0 * alpha0 + sum0;
        l1 = l1 * alpha1 + sum1;

#pragma unroll
        for (int j = 0; j < 8; j++) {
            ofr[j][0] *= alpha0; ofr[j][1] *= alpha0;
            ofr[j][2] *= alpha1; ofr[j][3] *= alpha1;
        }

#pragma unroll
        for (int u = 0; u < 8; u++) {
            uint32_t aPh[4], aPl[4];
            split_pack(sfr[2*u][0],   sfr[2*u][1],   aPh[0], aPl[0]);
            split_pack(sfr[2*u][2],   sfr[2*u][3],   aPh[1], aPl[1]);
            split_pack(sfr[2*u+1][0], sfr[2*u+1][1], aPh[2], aPl[2]);
            split_pack(sfr[2*u+1][2], sfr[2*u+1][3], aPh[3], aPl[3]);
#pragma unroll
            for (int cc = 0; cc < 4; cc++) {
                uint32_t bVh[4], bVl[4];
                const uint32_t voff =
                    (uint32_t)(((16 * u + lr) * ALD + 16 * cc + lc8) * 2);
                ldsm_x4_t(bVh, uVh + voff);
                ldsm_x4_t(bVl, uVl + voff);
                mma_bf16(ofr[2*cc],     aPh, bVh);
                mma_bf16(ofr[2*cc],     aPl, bVh);
                mma_bf16(ofr[2*cc],     aPh, bVl);
                mma_bf16(ofr[2*cc + 1], aPh, bVh + 2);
                mma_bf16(ofr[2*cc + 1], aPl, bVh + 2);
                mma_bf16(ofr[2*cc + 1], aPh, bVl + 2);
            }
        }
    }

    const float inv0 = 1.f / l0, inv1 = 1.f / l1;
    const int row0 = q0 + wid * 16 + g, row1 = row0 + 8;
#pragma unroll
    for (int j = 0; j < 8; j++) {
        const int c = h * HEAD_DIM + 8 * j + 2 * t;
        uint32_t hv, lv;
        split_pack(ofr[j][0] * inv0, ofr[j][1] * inv0, hv, lv);
        *(uint32_t*)(oh + (size_t)row0 * D_MODEL + c) = hv;
        *(uint32_t*)(ol + (size_t)row0 * D_MODEL + c) = lv;
        split_pack(ofr[j][2] * inv1, ofr[j][3] * inv1, hv, lv);
        *(uint32_t*)(oh + (size_t)row1 * D_MODEL + c) = hv;
        *(uint32_t*)(ol + (size_t)row1 * D_MODEL + c) = lv;
    }
}

// ---------------------------------------------------------------------------
extern "C" void kernel_launch(void* const* d_in, const int* in_sizes, int n_in,
                              void* d_out, int out_size)
{
    const float* x     = (const float*)d_in[0];
    const float* w_qkv = (const float*)d_in[1];
    const float* b_qkv = (const float*)d_in[2];
    const float* w_out = (const float*)d_in[3];
    const float* b_out = (const float*)d_in[4];
    float* out = (float*)d_out;

    __nv_bfloat16 *xh, *xl, *qh, *ql, *ah, *al, *wqh, *wql, *woh, *wol;
    cudaGetSymbolAddress((void**)&xh, g_xh);
    cudaGetSymbolAddress((void**)&xl, g_xl);
    cudaGetSymbolAddress((void**)&qh, g_qh);
    cudaGetSymbolAddress((void**)&ql, g_ql);
    cudaGetSymbolAddress((void**)&ah, g_ah);
    cudaGetSymbolAddress((void**)&al, g_al);
    cudaGetSymbolAddress((void**)&wqh, g_wqh);
    cudaGetSymbolAddress((void**)&wql, g_wql);
    cudaGetSymbolAddress((void**)&woh, g_woh);
    cudaGetSymbolAddress((void**)&wol, g_wol);

    cudaFuncSetAttribute(gemm_mma_kernel,
                         cudaFuncAttributeMaxDynamicSharedMemorySize, GEMM_SMEM);
    cudaFuncSetAttribute(flash_attn_mma_kernel,
                         cudaFuncAttributeMaxDynamicSharedMemorySize, FA_SMEM);

    {
        const int nx = S_LEN * D_MODEL;
        split_rows_kernel<<<nx / (256 * 4), 256>>>(x, xh, xl, nx);
        dim3 g1(QKV_COLS / 32, D_MODEL / 32), b1(32, 8);
        transpose_split_kernel<<<g1, b1>>>(w_qkv, wqh, wql, D_MODEL, QKV_COLS);
        dim3 g2(D_MODEL / 32, D_MODEL / 32);
        transpose_split_kernel<<<g2, b1>>>(w_out, woh, wol, D_MODEL, D_MODEL);
    }

    // 1) qkv (bf16 hi/lo) = x @ w_qkv + b_qkv
    {
        dim3 grid(QKV_COLS / 128, S_LEN / 128);
        gemm_mma_kernel<<<grid, 256, GEMM_SMEM>>>(xh, xl, wqh, wql, b_qkv,
                                                  nullptr, qh, ql, 1,
                                                  S_LEN, QKV_COLS, D_MODEL);
    }
    // 2) attention -> ah/al (bf16 hi/lo)
    {
        dim3 grid(S_LEN / 128, N_HEADS);
        flash_attn_mma_kernel<<<grid, 256, FA_SMEM>>>(qh, ql, ah, al);
    }
    // 3) out = attn @ w_out + b_out (fp32)
    {
        dim3 grid(D_MODEL / 128, S_LEN / 128);
        gemm_mma_kernel<<<grid, 256, GEMM_SMEM>>>(ah, al, woh, wol, b_out,
                                                  out, nullptr, nullptr, 0,
                                                  S_LEN, D_MODEL, D_MODEL);
    }
}

// round 13
// speedup vs baseline: 1.3900x; 1.3900x over previous
#include <cuda_runtime.h>
#include <cuda_fp16.h>
#include <cstdint>
#include <math.h>

#define S_LEN    4096
#define D_MODEL  1024
#define QKV_COLS 3072
#define N_HEADS  16
#define HEAD_DIM 64
#define ATT_SCALE 0.125f

// ---------------- scratch (__device__ globals; no cudaMalloc) ----------------
static __device__ __align__(256) __half g_xh[S_LEN * D_MODEL];
static __device__ __align__(256) __half g_xl[S_LEN * D_MODEL];
static __device__ __align__(256) __half g_qh[S_LEN * QKV_COLS];
static __device__ __align__(256) __half g_ql[S_LEN * QKV_COLS];
static __device__ __align__(256) __half g_ah[S_LEN * D_MODEL];
static __device__ __align__(256) __half g_al[S_LEN * D_MODEL];
static __device__ __align__(256) __half g_wqh[QKV_COLS * D_MODEL]; // [N][K] fp16
static __device__ __align__(256) __half g_woh[D_MODEL * D_MODEL];

// ---------------- PTX helpers ----------------
__device__ __forceinline__ uint32_t smem_u32(const void* p) {
    uint32_t a;
    asm("{ .reg .u64 t; cvta.to.shared.u64 t, %1; cvt.u32.u64 %0, t; }"
        : "=r"(a) : "l"(p));
    return a;
}
__device__ __forceinline__ void cp_async16(uint32_t saddr, const void* gptr) {
    asm volatile("cp.async.cg.shared.global [%0], [%1], 16;"
                 :: "r"(saddr), "l"(gptr));
}
#define CP_COMMIT() asm volatile("cp.async.commit_group;" ::: "memory")
#define CP_WAIT(n)  asm volatile("cp.async.wait_group %0;" :: "n"(n) : "memory")

__device__ __forceinline__ void ldsm_x4(uint32_t* r, uint32_t addr) {
    asm volatile("ldmatrix.sync.aligned.m8n8.x4.shared.b16 {%0,%1,%2,%3}, [%4];"
                 : "=r"(r[0]), "=r"(r[1]), "=r"(r[2]), "=r"(r[3]) : "r"(addr));
}
__device__ __forceinline__ void ldsm_x4_t(uint32_t* r, uint32_t addr) {
    asm volatile("ldmatrix.sync.aligned.m8n8.x4.trans.shared.b16 {%0,%1,%2,%3}, [%4];"
                 : "=r"(r[0]), "=r"(r[1]), "=r"(r[2]), "=r"(r[3]) : "r"(addr));
}
__device__ __forceinline__ void mma_f16(float* c, const uint32_t* a, const uint32_t* b) {
    asm volatile("mma.sync.aligned.m16n8k16.row.col.f32.f16.f16.f32 "
                 "{%0,%1,%2,%3}, {%4,%5,%6,%7}, {%8,%9}, {%0,%1,%2,%3};"
                 : "+f"(c[0]), "+f"(c[1]), "+f"(c[2]), "+f"(c[3])
                 : "r"(a[0]), "r"(a[1]), "r"(a[2]), "r"(a[3]), "r"(b[0]), "r"(b[1]));
}
// split two fp32 into packed fp16x2 hi + fp16x2 lo (hi+lo exact to ~2^-22)
__device__ __forceinline__ void split_pack_h(float x, float y, uint32_t& hi, uint32_t& lo) {
    __half hx = __float2half_rn(x), hy = __float2half_rn(y);
    __half lx = __float2half_rn(x - __half2float(hx));
    __half ly = __float2half_rn(y - __half2float(hy));
    hi = ((uint32_t)__half_as_ushort(hy) << 16) | __half_as_ushort(hx);
    lo = ((uint32_t)__half_as_ushort(ly) << 16) | __half_as_ushort(lx);
}

// ---------------- convert kernels ----------------
__global__ void split_rows_kernel(const float* __restrict__ src,
                                  __half* __restrict__ hi,
                                  __half* __restrict__ lo, int n)
{
    int i = (blockIdx.x * blockDim.x + threadIdx.x) * 4;
    if (i >= n) return;
    float4 v = *(const float4*)(src + i);
    __half h0 = __float2half_rn(v.x), h1 = __float2half_rn(v.y);
    __half h2 = __float2half_rn(v.z), h3 = __float2half_rn(v.w);
    hi[i] = h0; hi[i+1] = h1; hi[i+2] = h2; hi[i+3] = h3;
    lo[i]   = __float2half_rn(v.x - __half2float(h0));
    lo[i+1] = __float2half_rn(v.y - __half2float(h1));
    lo[i+2] = __float2half_rn(v.z - __half2float(h2));
    lo[i+3] = __float2half_rn(v.w - __half2float(h3));
}

// transpose + round: w[K][N] fp32 -> wT [N][K] fp16
__global__ void transpose_round_kernel(const float* __restrict__ w,
                                       __half* __restrict__ hi,
                                       int K, int N)
{
    __shared__ float tile[32][33];
    const int n0 = blockIdx.x * 32, k0 = blockIdx.y * 32;
    const int tx = threadIdx.x, ty = threadIdx.y;   // 32 x 8
#pragma unroll
    for (int i = 0; i < 4; i++)
        tile[ty + 8 * i][tx] = w[(size_t)(k0 + ty + 8 * i) * N + n0 + tx];
    __syncthreads();
#pragma unroll
    for (int i = 0; i < 4; i++) {
        const int r = ty + 8 * i;
        hi[(size_t)(n0 + r) * K + k0 + tx] = __float2half_rn(tile[tx][r]);
    }
}

// ---- raw mma.sync fp16 2-pass GEMM: C = (Ah+Al)·Bh^T + bias ----------------
// BK=32, 2-stage cp.async, 2 CTAs/SM. A split (exact), B rounded.
#define GLD 40                            // smem row stride (elems): 32 data + 8 pad
#define GTILE  (128 * GLD * 2)            // 10240 B per array
#define GSTAGE (3 * GTILE)                // 30720 B per stage (Ah, Al, Bh)
#define GEMM_SMEM (128 * 132 * 4)         // 67584 B (epilogue dominates; stages alias)

__global__ __launch_bounds__(256, 2)      // force <=128 regs -> 2 CTAs/SM
void gemm_mma_kernel(const __half* __restrict__ Ah,
                     const __half* __restrict__ Al,
                     const __half* __restrict__ Bh,
                     const float* __restrict__ bias,
                     float* __restrict__ Cf,
                     __half* __restrict__ Ch,
                     __half* __restrict__ Cl,
                     int hilo, int M, int N, int K)
{
    extern __shared__ char smraw[];
    float* Cs = (float*)smraw;
    const uint32_t sb = smem_u32(smraw);

    const int tid = threadIdx.x;
    const int wid = tid >> 5;
    const int lane = tid & 31;
    const int wr = wid >> 1;          // 0..3 -> m rows wr*32
    const int wc = wid & 1;           // 0..1 -> n cols wc*64
    const int g  = lane >> 2;
    const int t  = lane & 3;
    const int lr = lane & 15;
    const int lc8 = (lane >> 4) * 8;
    const int kk = (lane & 7) + ((lane & 16) >> 1);
    const int kd8 = lane & 8;
    const int m0 = blockIdx.y * 128, n0 = blockIdx.x * 128;

    float acc[16][4];
#pragma unroll
    for (int q = 0; q < 16; q++)
#pragma unroll
        for (int e = 0; e < 4; e++) acc[q][e] = 0.f;

    int crow[2], cbyte[2];
#pragma unroll
    for (int i = 0; i < 2; i++) {
        const int idx = tid + i * 256;     // 0..511
        crow[i]  = idx >> 2;               // 0..127
        cbyte[i] = (idx & 3) * 16;         // 0..48 bytes within k-tile
    }

    const int NT = K / 32;

    // prefetch stage 0
#pragma unroll
    for (int i = 0; i < 2; i++) {
        const int r = crow[i];
        const int gcol = cbyte[i] / 2;
        const uint32_t so = (uint32_t)(r * GLD * 2 + cbyte[i]);
        cp_async16(sb + so,             Ah + (size_t)(m0 + r) * K + gcol);
        cp_async16(sb + GTILE + so,     Al + (size_t)(m0 + r) * K + gcol);
        cp_async16(sb + 2 * GTILE + so, Bh + (size_t)(n0 + r) * K + gcol);
    }
    CP_COMMIT();

    for (int kt = 0; kt < NT; kt++) {
        __syncthreads();   // next-stage buffer free
        if (kt + 1 < NT) {
            const int k1 = (kt + 1) * 32;
            const uint32_t st = sb + ((kt + 1) & 1) * GSTAGE;
#pragma unroll
            for (int i = 0; i < 2; i++) {
                const int r = crow[i];
                const int gcol = k1 + cbyte[i] / 2;
                const uint32_t so = (uint32_t)(r * GLD * 2 + cbyte[i]);
                cp_async16(st + so,             Ah + (size_t)(m0 + r) * K + gcol);
                cp_async16(st + GTILE + so,     Al + (size_t)(m0 + r) * K + gcol);
                cp_async16(st + 2 * GTILE + so, Bh + (size_t)(n0 + r) * K + gcol);
            }
            CP_COMMIT();
            CP_WAIT(1);
        } else {
            CP_WAIT(0);
        }
        __syncthreads();   // stage kt visible

        const uint32_t uAh = sb + (kt & 1) * GSTAGE;
        const uint32_t uAl = uAh + GTILE;
        const uint32_t uBh = uAh + 2 * GTILE;

#pragma unroll
        for (int sub = 0; sub < 2; sub++) {
            const int kc = sub * 16;
            uint32_t ah[2][4], al[2][4];
#pragma unroll
            for (int i = 0; i < 2; i++) {
                const uint32_t aoff =
                    (uint32_t)(((wr * 32 + i * 16 + lr) * GLD + kc + lc8) * 2);
                ldsm_x4(ah[i], uAh + aoff);
                ldsm_x4(al[i], uAl + aoff);
            }
#pragma unroll
            for (int jj = 0; jj < 4; jj++) {
                uint32_t bh[4];
                const uint32_t boff =
                    (uint32_t)(((wc * 64 + jj * 16 + kk) * GLD + kc + kd8) * 2);
                ldsm_x4(bh, uBh + boff);
#pragma unroll
                for (int i = 0; i < 2; i++) {
                    float* c0 = acc[i * 8 + 2 * jj];
                    float* c1 = acc[i * 8 + 2 * jj + 1];
                    mma_f16(c0, ah[i], bh);
                    mma_f16(c0, al[i], bh);
                    mma_f16(c1, ah[i], bh + 2);
                    mma_f16(c1, al[i], bh + 2);
                }
            }
        }
    }

    __syncthreads();   // all ldsm done before Cs overwrites stage smem
#pragma unroll
    for (int i = 0; i < 2; i++)
#pragma unroll
        for (int f = 0; f < 8; f++) {
            const int row = wr * 32 + i * 16 + g;
            const int col = wc * 64 + 8 * f + 2 * t;
            const float* c = acc[i * 8 + f];
            *(float2*)&Cs[row * 132 + col]       = make_float2(c[0], c[1]);
            *(float2*)&Cs[(row + 8) * 132 + col] = make_float2(c[2], c[3]);
        }
    __syncthreads();

    {
        const int r = tid >> 1;
        const int cb = (tid & 1) * 64;
        const float* bp = bias + n0 + cb;
        const float* sp = &Cs[r * 132 + cb];
        if (!hilo) {
            float* cp = Cf + (size_t)(m0 + r) * N + n0 + cb;
#pragma unroll
            for (int j = 0; j < 64; j += 4) {
                float4 o;
                o.x = sp[j+0] + bp[j+0]; o.y = sp[j+1] + bp[j+1];
                o.z = sp[j+2] + bp[j+2]; o.w = sp[j+3] + bp[j+3];
                *(float4*)(cp + j) = o;
            }
        } else {
            __half* hp = Ch + (size_t)(m0 + r) * N + n0 + cb;
            __half* lp = Cl + (size_t)(m0 + r) * N + n0 + cb;
#pragma unroll
            for (int j = 0; j < 64; j += 4) {
                uint32_t h0, l0, h1, l1;
                split_pack_h(sp[j+0] + bp[j+0], sp[j+1] + bp[j+1], h0, l0);
                split_pack_h(sp[j+2] + bp[j+2], sp[j+3] + bp[j+3], h1, l1);
                *(uint2*)(hp + j) = make_uint2(h0, h1);
                *(uint2*)(lp + j) = make_uint2(l0, l1);
            }
        }
    }
}

// ---------------------------------------------------------------------------
// Flash attention fp16: Q split (exact), K/V rounded single fp16; 2-pass QK/PV.
// Grid (32, 16), block 256 = 8 warps; warp owns 16 q-rows x 128-key tile.
// ---------------------------------------------------------------------------
#define ALD 72                              // fp16 elems per smem row
#define FARR (128 * ALD * 2)                // 18432 B per array
#define FA_KVSTAGE (2 * FARR)               // Kh Vh = 36864 B
#define FA_KVBASE  (2 * FARR)               // after Qh Ql
#define FA_SMEM (FA_KVBASE + 2 * FA_KVSTAGE)  // 110592 B

__global__ __launch_bounds__(256, 1)
void flash_attn_mma_kernel(const __half* __restrict__ qh,
                           const __half* __restrict__ ql,
                           __half* __restrict__ oh,
                           __half* __restrict__ ol)
{
    extern __shared__ char smraw[];
    __half* sQh = (__half*)smraw;
    __half* sQl = sQh + 128 * ALD;
    const uint32_t sb = smem_u32(smraw);

    const int qb  = gridDim.x - 1 - blockIdx.x;   // long rows first
    const int h   = blockIdx.y;
    const int tid = threadIdx.x;
    const int wid = tid >> 5;
    const int lane = tid & 31;
    const int q0  = qb * 128;

    const int g  = lane >> 2;
    const int t  = lane & 3;
    const int lr = lane & 15;
    const int lc8 = (lane >> 4) * 8;
    const int kk = (lane & 7) + ((lane & 16) >> 1);
    const int kd8 = lane & 8;

    const int colK = D_MODEL + h * HEAD_DIM;
    const int colV = 2 * D_MODEL + h * HEAD_DIM;

    int crow[4], cbyte[4];
#pragma unroll
    for (int i = 0; i < 4; i++) {
        const int idx = tid + i * 256;
        crow[i]  = idx >> 3;
        cbyte[i] = (idx & 7) * 16;
    }

    // ---- load Q tile (hi/lo) ----
#pragma unroll
    for (int i = 0; i < 4; i++) {
        const int r = crow[i], c = cbyte[i] / 2;
        const size_t gofs = (size_t)(q0 + r) * QKV_COLS + h * HEAD_DIM + c;
        *(uint4*)(sQh + r * ALD + c) = *(const uint4*)(qh + gofs);
        *(uint4*)(sQl + r * ALD + c) = *(const uint4*)(ql + gofs);
    }

    // ---- prefetch K/V stage 0 (hi only) ----
    {
        const uint32_t st = sb + FA_KVBASE;
#pragma unroll
        for (int i = 0; i < 4; i++) {
            const int r = crow[i];
            const uint32_t so = (uint32_t)(r * ALD * 2 + cbyte[i]);
            const size_t gr = (size_t)r * QKV_COLS;
            const int c = cbyte[i] / 2;
            cp_async16(st + so,        qh + gr + colK + c);
            cp_async16(st + FARR + so, qh + gr + colV + c);
        }
        CP_COMMIT();
    }

    float ofr[8][4];
    float m0 = -1e30f, m1 = -1e30f, l0 = 0.f, l1 = 0.f;
#pragma unroll
    for (int j = 0; j < 8; j++)
#pragma unroll
        for (int e = 0; e < 4; e++) ofr[j][e] = 0.f;

    for (int kt = 0; kt <= qb; kt++) {
        __syncthreads();
        if (kt + 1 <= qb) {
            const int k1 = (kt + 1) * 128;
            const uint32_t st = sb + FA_KVBASE + ((kt + 1) & 1) * FA_KVSTAGE;
#pragma unroll
            for (int i = 0; i < 4; i++) {
                const int r = crow[i];
                const uint32_t so = (uint32_t)(r * ALD * 2 + cbyte[i]);
                const size_t gr = (size_t)(k1 + r) * QKV_COLS;
                const int c = cbyte[i] / 2;
                cp_async16(st + so,        qh + gr + colK + c);
                cp_async16(st + FARR + so, qh + gr + colV + c);
            }
            CP_COMMIT();
            CP_WAIT(1);
        } else {
            CP_WAIT(0);
        }
        __syncthreads();

        const uint32_t stg = sb + FA_KVBASE + (kt & 1) * FA_KVSTAGE;
        const uint32_t uKh = stg, uVh = stg + FARR;
        const uint32_t uQh = sb, uQl = sb + FARR;

        // ---- S = (Qh+Ql)·Kh^T : 2-pass ----
        float sfr[16][4];
#pragma unroll
        for (int j = 0; j < 16; j++)
#pragma unroll
            for (int e = 0; e < 4; e++) sfr[j][e] = 0.f;

#pragma unroll
        for (int u = 0; u < 4; u++) {
            uint32_t aQh[4], aQl[4];
            const uint32_t qoff =
                (uint32_t)(((wid * 16 + lr) * ALD + 16 * u + lc8) * 2);
            ldsm_x4(aQh, uQh + qoff);
            ldsm_x4(aQl, uQl + qoff);
#pragma unroll
            for (int jj = 0; jj < 8; jj++) {
                uint32_t bKh[4];
                const uint32_t koff =
                    (uint32_t)(((16 * jj + kk) * ALD + 16 * u + kd8) * 2);
                ldsm_x4(bKh, uKh + koff);
                mma_f16(sfr[2*jj],   aQh, bKh);
                mma_f16(sfr[2*jj],   aQl, bKh);
                mma_f16(sfr[2*jj+1], aQh, bKh + 2);
                mma_f16(sfr[2*jj+1], aQl, bKh + 2);
            }
        }

        // ---- scale + causal mask ----
        if (kt == qb) {
            const int gq0 = wid * 16 + g, gq1 = gq0 + 8;
#pragma unroll
            for (int j = 0; j < 16; j++) {
                const int c = 8 * j + 2 * t;
                sfr[j][0] = (c     <= gq0) ? sfr[j][0] * ATT_SCALE : -1e30f;
                sfr[j][1] = (c + 1 <= gq0) ? sfr[j][1] * ATT_SCALE : -1e30f;
                sfr[j][2] = (c     <= gq1) ? sfr[j][2] * ATT_SCALE : -1e30f;
                sfr[j][3] = (c + 1 <= gq1) ? sfr[j][3] * ATT_SCALE : -1e30f;
            }
        } else {
#pragma unroll
            for (int j = 0; j < 16; j++) {
                sfr[j][0] *= ATT_SCALE; sfr[j][1] *= ATT_SCALE;
                sfr[j][2] *= ATT_SCALE; sfr[j][3] *= ATT_SCALE;
            }
        }

        // ---- online softmax ----
        float mn0 = m0, mn1 = m1;
#pragma unroll
        for (int j = 0; j < 16; j++) {
            mn0 = fmaxf(mn0, fmaxf(sfr[j][0], sfr[j][1]));
            mn1 = fmaxf(mn1, fmaxf(sfr[j][2], sfr[j][3]));
        }
        mn0 = fmaxf(mn0, __shfl_xor_sync(0xffffffffu, mn0, 1));
        mn0 = fmaxf(mn0, __shfl_xor_sync(0xffffffffu, mn0, 2));
        mn1 = fmaxf(mn1, __shfl_xor_sync(0xffffffffu, mn1, 1));
        mn1 = fmaxf(mn1, __shfl_xor_sync(0xffffffffu, mn1, 2));

        const float alpha0 = __expf(m0 - mn0);
        const float alpha1 = __expf(m1 - mn1);
        m0 = mn0; m1 = mn1;

        float sum0 = 0.f, sum1 = 0.f;
#pragma unroll
        for (int j = 0; j < 16; j++) {
            sfr[j][0] = __expf(sfr[j][0] - mn0);
            sfr[j][1] = __expf(sfr[j][1] - mn0);
            sfr[j][2] = __expf(sfr[j][2] - mn1);
            sfr[j][3] = __expf(sfr[j][3] - mn1);
            sum0 += sfr[j][0] + sfr[j][1];
            sum1 += sfr[j][2] + sfr[j][3];
        }
        sum0 += __shfl_xor_sync(0xffffffffu, sum0, 1);
        sum0 += __shfl_xor_sync(0xffffffffu, sum0, 2);
        sum1 += __shfl_xor_sync(0xffffffffu, sum1, 1);
        sum1 += __shfl_xor_sync(0xffffffffu, sum1, 2);
        l0 = l0 * alpha0 + sum0;
        l1 = l1 * alpha1 + sum1;

#pragma unroll
        for (int j = 0; j < 8; j++) {
            ofr[j][0] *= alpha0; ofr[j][1] *= alpha0;
            ofr[j][2] *= alpha1; ofr[j][3] *= alpha1;
        }

        // ---- O += (Ph+Pl)·Vh : 2-pass ----
#pragma unroll
        for (int u = 0; u < 8; u++) {
            uint32_t aPh[4], aPl[4];
            split_pack_h(sfr[2*u][0],   sfr[2*u][1],   aPh[0], aPl[0]);
            split_pack_h(sfr[2*u][2],   sfr[2*u][3],   aPh[1], aPl[1]);
            split_pack_h(sfr[2*u+1][0], sfr[2*u+1][1], aPh[2], aPl[2]);
            split_pack_h(sfr[2*u+1][2], sfr[2*u+1][3], aPh[3], aPl[3]);
#pragma unroll
            for (int cc = 0; cc < 4; cc++) {
                uint32_t bVh[4];
                const uint32_t voff =
                    (uint32_t)(((16 * u + lr) * ALD + 16 * cc + lc8) * 2);
                ldsm_x4_t(bVh, uVh + voff);
                mma_f16(ofr[2*cc],     aPh, bVh);
                mma_f16(ofr[2*cc],     aPl, bVh);
                mma_f16(ofr[2*cc + 1], aPh, bVh + 2);
                mma_f16(ofr[2*cc + 1], aPl, bVh + 2);
            }
        }
    }

    // ---- epilogue: normalize, split fp16 hi/lo, store ----
    const float inv0 = 1.f / l0, inv1 = 1.f / l1;
    const int row0 = q0 + wid * 16 + g, row1 = row0 + 8;
#pragma unroll
    for (int j = 0; j < 8; j++) {
        const int c = h * HEAD_DIM + 8 * j + 2 * t;
        uint32_t hv, lv;
        split_pack_h(ofr[j][0] * inv0, ofr[j][1] * inv0, hv, lv);
        *(uint32_t*)(oh + (size_t)row0 * D_MODEL + c) = hv;
        *(uint32_t*)(ol + (size_t)row0 * D_MODEL + c) = lv;
        split_pack_h(ofr[j][2] * inv1, ofr[j][3] * inv1, hv, lv);
        *(uint32_t*)(oh + (size_t)row1 * D_MODEL + c) = hv;
        *(uint32_t*)(ol + (size_t)row1 * D_MODEL + c) = lv;
    }
}

// ---------------------------------------------------------------------------
extern "C" void kernel_launch(void* const* d_in, const int* in_sizes, int n_in,
                              void* d_out, int out_size)
{
    const float* x     = (const float*)d_in[0];
    const float* w_qkv = (const float*)d_in[1];
    const float* b_qkv = (const float*)d_in[2];
    const float* w_out = (const float*)d_in[3];
    const float* b_out = (const float*)d_in[4];
    float* out = (float*)d_out;

    __half *xh, *xl, *qh, *ql, *ah, *al, *wqh, *woh;
    cudaGetSymbolAddress((void**)&xh, g_xh);
    cudaGetSymbolAddress((void**)&xl, g_xl);
    cudaGetSymbolAddress((void**)&qh, g_qh);
    cudaGetSymbolAddress((void**)&ql, g_ql);
    cudaGetSymbolAddress((void**)&ah, g_ah);
    cudaGetSymbolAddress((void**)&al, g_al);
    cudaGetSymbolAddress((void**)&wqh, g_wqh);
    cudaGetSymbolAddress((void**)&woh, g_woh);

    cudaFuncSetAttribute(gemm_mma_kernel,
                         cudaFuncAttributeMaxDynamicSharedMemorySize, GEMM_SMEM);
    cudaFuncSetAttribute(flash_attn_mma_kernel,
                         cudaFuncAttributeMaxDynamicSharedMemorySize, FA_SMEM);

    {
        const int nx = S_LEN * D_MODEL;
        split_rows_kernel<<<nx / (256 * 4), 256>>>(x, xh, xl, nx);
        dim3 g1(QKV_COLS / 32, D_MODEL / 32), b1(32, 8);
        transpose_round_kernel<<<g1, b1>>>(w_qkv, wqh, D_MODEL, QKV_COLS);
        dim3 g2(D_MODEL / 32, D_MODEL / 32);
        transpose_round_kernel<<<g2, b1>>>(w_out, woh, D_MODEL, D_MODEL);
    }

    // 1) qkv (fp16 hi/lo) = (xh+xl) @ wqh + b_qkv
    {
        dim3 grid(QKV_COLS / 128, S_LEN / 128);
        gemm_mma_kernel<<<grid, 256, GEMM_SMEM>>>(xh, xl, wqh, b_qkv,
                                                  nullptr, qh, ql, 1,
                                                  S_LEN, QKV_COLS, D_MODEL);
    }
    // 2) attention -> ah/al (fp16 hi/lo)
    {
        dim3 grid(S_LEN / 128, N_HEADS);
        flash_attn_mma_kernel<<<grid, 256, FA_SMEM>>>(qh, ql, ah, al);
    }
    // 3) out = (ah+al) @ woh + b_out (fp32)
    {
        dim3 grid(D_MODEL / 128, S_LEN / 128);
        gemm_mma_kernel<<<grid, 256, GEMM_SMEM>>>(ah, al, woh, b_out,
                                                  out, nullptr, nullptr, 0,
                                                  S_LEN, D_MODEL, D_MODEL);
    }
}

// round 14
// speedup vs baseline: 1.7005x; 1.2233x over previous
#include <cuda_runtime.h>
#include <cuda_fp16.h>
#include <cstdint>
#include <math.h>

#define S_LEN    4096
#define D_MODEL  1024
#define QKV_COLS 3072
#define N_HEADS  16
#define HEAD_DIM 64
#define ATT_SCALE 0.125f

// ---------------- scratch (__device__ globals; no cudaMalloc) ----------------
static __device__ __align__(256) __half g_xh[S_LEN * D_MODEL];
static __device__ __align__(256) __half g_xl[S_LEN * D_MODEL];
static __device__ __align__(256) __half g_qkv[S_LEN * QKV_COLS];   // fp16 qkv
static __device__ __align__(256) __half g_ah[S_LEN * D_MODEL];
static __device__ __align__(256) __half g_al[S_LEN * D_MODEL];
static __device__ __align__(256) __half g_wqh[QKV_COLS * D_MODEL]; // [N][K] fp16
static __device__ __align__(256) __half g_woh[D_MODEL * D_MODEL];

// ---------------- PTX helpers ----------------
__device__ __forceinline__ uint32_t smem_u32(const void* p) {
    uint32_t a;
    asm("{ .reg .u64 t; cvta.to.shared.u64 t, %1; cvt.u32.u64 %0, t; }"
        : "=r"(a) : "l"(p));
    return a;
}
__device__ __forceinline__ void cp_async16(uint32_t saddr, const void* gptr) {
    asm volatile("cp.async.cg.shared.global [%0], [%1], 16;"
                 :: "r"(saddr), "l"(gptr));
}
#define CP_COMMIT() asm volatile("cp.async.commit_group;" ::: "memory")
#define CP_WAIT(n)  asm volatile("cp.async.wait_group %0;" :: "n"(n) : "memory")

__device__ __forceinline__ void ldsm_x4(uint32_t* r, uint32_t addr) {
    asm volatile("ldmatrix.sync.aligned.m8n8.x4.shared.b16 {%0,%1,%2,%3}, [%4];"
                 : "=r"(r[0]), "=r"(r[1]), "=r"(r[2]), "=r"(r[3]) : "r"(addr));
}
__device__ __forceinline__ void ldsm_x4_t(uint32_t* r, uint32_t addr) {
    asm volatile("ldmatrix.sync.aligned.m8n8.x4.trans.shared.b16 {%0,%1,%2,%3}, [%4];"
                 : "=r"(r[0]), "=r"(r[1]), "=r"(r[2]), "=r"(r[3]) : "r"(addr));
}
__device__ __forceinline__ void mma_f16(float* c, const uint32_t* a, const uint32_t* b) {
    asm volatile("mma.sync.aligned.m16n8k16.row.col.f32.f16.f16.f32 "
                 "{%0,%1,%2,%3}, {%4,%5,%6,%7}, {%8,%9}, {%0,%1,%2,%3};"
                 : "+f"(c[0]), "+f"(c[1]), "+f"(c[2]), "+f"(c[3])
                 : "r"(a[0]), "r"(a[1]), "r"(a[2]), "r"(a[3]), "r"(b[0]), "r"(b[1]));
}
// split two fp32 into packed fp16x2 hi + fp16x2 lo
__device__ __forceinline__ void split_pack_h(float x, float y, uint32_t& hi, uint32_t& lo) {
    __half hx = __float2half_rn(x), hy = __float2half_rn(y);
    __half lx = __float2half_rn(x - __half2float(hx));
    __half ly = __float2half_rn(y - __half2float(hy));
    hi = ((uint32_t)__half_as_ushort(hy) << 16) | __half_as_ushort(hx);
    lo = ((uint32_t)__half_as_ushort(ly) << 16) | __half_as_ushort(lx);
}
// round two fp32 to packed fp16x2
__device__ __forceinline__ uint32_t pack_h(float x, float y) {
    __half hx = __float2half_rn(x), hy = __float2half_rn(y);
    return ((uint32_t)__half_as_ushort(hy) << 16) | __half_as_ushort(hx);
}

// ---------------- convert kernels ----------------
__global__ void split_rows_kernel(const float* __restrict__ src,
                                  __half* __restrict__ hi,
                                  __half* __restrict__ lo, int n)
{
    int i = (blockIdx.x * blockDim.x + threadIdx.x) * 4;
    if (i >= n) return;
    float4 v = *(const float4*)(src + i);
    __half h0 = __float2half_rn(v.x), h1 = __float2half_rn(v.y);
    __half h2 = __float2half_rn(v.z), h3 = __float2half_rn(v.w);
    hi[i] = h0; hi[i+1] = h1; hi[i+2] = h2; hi[i+3] = h3;
    lo[i]   = __float2half_rn(v.x - __half2float(h0));
    lo[i+1] = __float2half_rn(v.y - __half2float(h1));
    lo[i+2] = __float2half_rn(v.z - __half2float(h2));
    lo[i+3] = __float2half_rn(v.w - __half2float(h3));
}

__global__ void transpose_round_kernel(const float* __restrict__ w,
                                       __half* __restrict__ hi,
                                       int K, int N)
{
    __shared__ float tile[32][33];
    const int n0 = blockIdx.x * 32, k0 = blockIdx.y * 32;
    const int tx = threadIdx.x, ty = threadIdx.y;   // 32 x 8
#pragma unroll
    for (int i = 0; i < 4; i++)
        tile[ty + 8 * i][tx] = w[(size_t)(k0 + ty + 8 * i) * N + n0 + tx];
    __syncthreads();
#pragma unroll
    for (int i = 0; i < 4; i++) {
        const int r = ty + 8 * i;
        hi[(size_t)(n0 + r) * K + k0 + tx] = __float2half_rn(tile[tx][r]);
    }
}

// ---- raw mma.sync fp16 2-pass GEMM: C = (Ah+Al)·Bh^T + bias ----------------
// hilo: 0 = fp32 out, 1 = fp16 hi/lo out, 2 = fp16 (rounded) out
#define GLD 40
#define GTILE  (128 * GLD * 2)            // 10240 B per array
#define GSTAGE (3 * GTILE)                // 30720 B per stage (Ah, Al, Bh)
#define GEMM_SMEM (128 * 132 * 4)         // 67584 B (epilogue dominates; stages alias)

__global__ __launch_bounds__(256, 2)      // force <=128 regs -> 2 CTAs/SM
void gemm_mma_kernel(const __half* __restrict__ Ah,
                     const __half* __restrict__ Al,
                     const __half* __restrict__ Bh,
                     const float* __restrict__ bias,
                     float* __restrict__ Cf,
                     __half* __restrict__ Ch,
                     __half* __restrict__ Cl,
                     int hilo, int M, int N, int K)
{
    extern __shared__ char smraw[];
    float* Cs = (float*)smraw;
    const uint32_t sb = smem_u32(smraw);

    const int tid = threadIdx.x;
    const int wid = tid >> 5;
    const int lane = tid & 31;
    const int wr = wid >> 1;
    const int wc = wid & 1;
    const int g  = lane >> 2;
    const int t  = lane & 3;
    const int lr = lane & 15;
    const int lc8 = (lane >> 4) * 8;
    const int kk = (lane & 7) + ((lane & 16) >> 1);
    const int kd8 = lane & 8;
    const int m0 = blockIdx.y * 128, n0 = blockIdx.x * 128;

    float acc[16][4];
#pragma unroll
    for (int q = 0; q < 16; q++)
#pragma unroll
        for (int e = 0; e < 4; e++) acc[q][e] = 0.f;

    int crow[2], cbyte[2];
#pragma unroll
    for (int i = 0; i < 2; i++) {
        const int idx = tid + i * 256;
        crow[i]  = idx >> 2;
        cbyte[i] = (idx & 3) * 16;
    }

    const int NT = K / 32;

    // prefetch stage 0
#pragma unroll
    for (int i = 0; i < 2; i++) {
        const int r = crow[i];
        const int gcol = cbyte[i] / 2;
        const uint32_t so = (uint32_t)(r * GLD * 2 + cbyte[i]);
        cp_async16(sb + so,             Ah + (size_t)(m0 + r) * K + gcol);
        cp_async16(sb + GTILE + so,     Al + (size_t)(m0 + r) * K + gcol);
        cp_async16(sb + 2 * GTILE + so, Bh + (size_t)(n0 + r) * K + gcol);
    }
    CP_COMMIT();

    for (int kt = 0; kt < NT; kt++) {
        __syncthreads();
        if (kt + 1 < NT) {
            const int k1 = (kt + 1) * 32;
            const uint32_t st = sb + ((kt + 1) & 1) * GSTAGE;
#pragma unroll
            for (int i = 0; i < 2; i++) {
                const int r = crow[i];
                const int gcol = k1 + cbyte[i] / 2;
                const uint32_t so = (uint32_t)(r * GLD * 2 + cbyte[i]);
                cp_async16(st + so,             Ah + (size_t)(m0 + r) * K + gcol);
                cp_async16(st + GTILE + so,     Al + (size_t)(m0 + r) * K + gcol);
                cp_async16(st + 2 * GTILE + so, Bh + (size_t)(n0 + r) * K + gcol);
            }
            CP_COMMIT();
            CP_WAIT(1);
        } else {
            CP_WAIT(0);
        }
        __syncthreads();

        const uint32_t uAh = sb + (kt & 1) * GSTAGE;
        const uint32_t uAl = uAh + GTILE;
        const uint32_t uBh = uAh + 2 * GTILE;

#pragma unroll
        for (int sub = 0; sub < 2; sub++) {
            const int kc = sub * 16;
            uint32_t ah[2][4], al[2][4];
#pragma unroll
            for (int i = 0; i < 2; i++) {
                const uint32_t aoff =
                    (uint32_t)(((wr * 32 + i * 16 + lr) * GLD + kc + lc8) * 2);
                ldsm_x4(ah[i], uAh + aoff);
                ldsm_x4(al[i], uAl + aoff);
            }
#pragma unroll
            for (int jj = 0; jj < 4; jj++) {
                uint32_t bh[4];
                const uint32_t boff =
                    (uint32_t)(((wc * 64 + jj * 16 + kk) * GLD + kc + kd8) * 2);
                ldsm_x4(bh, uBh + boff);
#pragma unroll
                for (int i = 0; i < 2; i++) {
                    float* c0 = acc[i * 8 + 2 * jj];
                    float* c1 = acc[i * 8 + 2 * jj + 1];
                    mma_f16(c0, ah[i], bh);
                    mma_f16(c0, al[i], bh);
                    mma_f16(c1, ah[i], bh + 2);
                    mma_f16(c1, al[i], bh + 2);
                }
            }
        }
    }

    __syncthreads();
#pragma unroll
    for (int i = 0; i < 2; i++)
#pragma unroll
        for (int f = 0; f < 8; f++) {
            const int row = wr * 32 + i * 16 + g;
            const int col = wc * 64 + 8 * f + 2 * t;
            const float* c = acc[i * 8 + f];
            *(float2*)&Cs[row * 132 + col]       = make_float2(c[0], c[1]);
            *(float2*)&Cs[(row + 8) * 132 + col] = make_float2(c[2], c[3]);
        }
    __syncthreads();

    {
        const int r = tid >> 1;
        const int cb = (tid & 1) * 64;
        const float* bp = bias + n0 + cb;
        const float* sp = &Cs[r * 132 + cb];
        if (hilo == 0) {
            float* cp = Cf + (size_t)(m0 + r) * N + n0 + cb;
#pragma unroll
            for (int j = 0; j < 64; j += 4) {
                float4 o;
                o.x = sp[j+0] + bp[j+0]; o.y = sp[j+1] + bp[j+1];
                o.z = sp[j+2] + bp[j+2]; o.w = sp[j+3] + bp[j+3];
                *(float4*)(cp + j) = o;
            }
        } else if (hilo == 1) {
            __half* hp = Ch + (size_t)(m0 + r) * N + n0 + cb;
            __half* lp = Cl + (size_t)(m0 + r) * N + n0 + cb;
#pragma unroll
            for (int j = 0; j < 64; j += 4) {
                uint32_t h0, l0, h1, l1;
                split_pack_h(sp[j+0] + bp[j+0], sp[j+1] + bp[j+1], h0, l0);
                split_pack_h(sp[j+2] + bp[j+2], sp[j+3] + bp[j+3], h1, l1);
                *(uint2*)(hp + j) = make_uint2(h0, h1);
                *(uint2*)(lp + j) = make_uint2(l0, l1);
            }
        } else {
            __half* hp = Ch + (size_t)(m0 + r) * N + n0 + cb;
#pragma unroll
            for (int j = 0; j < 64; j += 4) {
                uint32_t h0 = pack_h(sp[j+0] + bp[j+0], sp[j+1] + bp[j+1]);
                uint32_t h1 = pack_h(sp[j+2] + bp[j+2], sp[j+3] + bp[j+3]);
                *(uint2*)(hp + j) = make_uint2(h0, h1);
            }
        }
    }
}

// ---------------------------------------------------------------------------
// Flash attention fp16, 1-pass QK and PV (Q, K, V, P all rounded fp16).
// Grid (32, 16), block 256 = 8 warps; warp owns 16 q-rows x 128-key tile.
// ---------------------------------------------------------------------------
#define ALD 72                              // fp16 elems per smem row
#define FARR (128 * ALD * 2)                // 18432 B per array
#define FA_KVSTAGE (2 * FARR)               // Kh Vh = 36864 B
#define FA_KVBASE  FARR                     // after Qh
#define FA_SMEM (FA_KVBASE + 2 * FA_KVSTAGE)  // 92160 B

__global__ __launch_bounds__(256, 1)
void flash_attn_mma_kernel(const __half* __restrict__ qkv,
                           __half* __restrict__ oh,
                           __half* __restrict__ ol)
{
    extern __shared__ char smraw[];
    __half* sQh = (__half*)smraw;
    const uint32_t sb = smem_u32(smraw);

    const int qb  = gridDim.x - 1 - blockIdx.x;   // long rows first
    const int h   = blockIdx.y;
    const int tid = threadIdx.x;
    const int wid = tid >> 5;
    const int lane = tid & 31;
    const int q0  = qb * 128;

    const int g  = lane >> 2;
    const int t  = lane & 3;
    const int lr = lane & 15;
    const int lc8 = (lane >> 4) * 8;
    const int kk = (lane & 7) + ((lane & 16) >> 1);
    const int kd8 = lane & 8;

    const int colK = D_MODEL + h * HEAD_DIM;
    const int colV = 2 * D_MODEL + h * HEAD_DIM;

    int crow[4], cbyte[4];
#pragma unroll
    for (int i = 0; i < 4; i++) {
        const int idx = tid + i * 256;
        crow[i]  = idx >> 3;
        cbyte[i] = (idx & 7) * 16;
    }

    // ---- load Q tile ----
#pragma unroll
    for (int i = 0; i < 4; i++) {
        const int r = crow[i], c = cbyte[i] / 2;
        const size_t gofs = (size_t)(q0 + r) * QKV_COLS + h * HEAD_DIM + c;
        *(uint4*)(sQh + r * ALD + c) = *(const uint4*)(qkv + gofs);
    }

    // ---- prefetch K/V stage 0 ----
    {
        const uint32_t st = sb + FA_KVBASE;
#pragma unroll
        for (int i = 0; i < 4; i++) {
            const int r = crow[i];
            const uint32_t so = (uint32_t)(r * ALD * 2 + cbyte[i]);
            const size_t gr = (size_t)r * QKV_COLS;
            const int c = cbyte[i] / 2;
            cp_async16(st + so,        qkv + gr + colK + c);
            cp_async16(st + FARR + so, qkv + gr + colV + c);
        }
        CP_COMMIT();
    }

    float ofr[8][4];
    float m0 = -1e30f, m1 = -1e30f, l0 = 0.f, l1 = 0.f;
#pragma unroll
    for (int j = 0; j < 8; j++)
#pragma unroll
        for (int e = 0; e < 4; e++) ofr[j][e] = 0.f;

    for (int kt = 0; kt <= qb; kt++) {
        __syncthreads();
        if (kt + 1 <= qb) {
            const int k1 = (kt + 1) * 128;
            const uint32_t st = sb + FA_KVBASE + ((kt + 1) & 1) * FA_KVSTAGE;
#pragma unroll
            for (int i = 0; i < 4; i++) {
                const int r = crow[i];
                const uint32_t so = (uint32_t)(r * ALD * 2 + cbyte[i]);
                const size_t gr = (size_t)(k1 + r) * QKV_COLS;
                const int c = cbyte[i] / 2;
                cp_async16(st + so,        qkv + gr + colK + c);
                cp_async16(st + FARR + so, qkv + gr + colV + c);
            }
            CP_COMMIT();
            CP_WAIT(1);
        } else {
            CP_WAIT(0);
        }
        __syncthreads();

        const uint32_t stg = sb + FA_KVBASE + (kt & 1) * FA_KVSTAGE;
        const uint32_t uKh = stg, uVh = stg + FARR;
        const uint32_t uQh = sb;

        // ---- S = Qh·Kh^T : 1-pass ----
        float sfr[16][4];
#pragma unroll
        for (int j = 0; j < 16; j++)
#pragma unroll
            for (int e = 0; e < 4; e++) sfr[j][e] = 0.f;

#pragma unroll
        for (int u = 0; u < 4; u++) {
            uint32_t aQh[4];
            const uint32_t qoff =
                (uint32_t)(((wid * 16 + lr) * ALD + 16 * u + lc8) * 2);
            ldsm_x4(aQh, uQh + qoff);
#pragma unroll
            for (int jj = 0; jj < 8; jj++) {
                uint32_t bKh[4];
                const uint32_t koff =
                    (uint32_t)(((16 * jj + kk) * ALD + 16 * u + kd8) * 2);
                ldsm_x4(bKh, uKh + koff);
                mma_f16(sfr[2*jj],   aQh, bKh);
                mma_f16(sfr[2*jj+1], aQh, bKh + 2);
            }
        }

        // ---- scale + causal mask ----
        if (kt == qb) {
            const int gq0 = wid * 16 + g, gq1 = gq0 + 8;
#pragma unroll
            for (int j = 0; j < 16; j++) {
                const int c = 8 * j + 2 * t;
                sfr[j][0] = (c     <= gq0) ? sfr[j][0] * ATT_SCALE : -1e30f;
                sfr[j][1] = (c + 1 <= gq0) ? sfr[j][1] * ATT_SCALE : -1e30f;
                sfr[j][2] = (c     <= gq1) ? sfr[j][2] * ATT_SCALE : -1e30f;
                sfr[j][3] = (c + 1 <= gq1) ? sfr[j][3] * ATT_SCALE : -1e30f;
            }
        } else {
#pragma unroll
            for (int j = 0; j < 16; j++) {
                sfr[j][0] *= ATT_SCALE; sfr[j][1] *= ATT_SCALE;
                sfr[j][2] *= ATT_SCALE; sfr[j][3] *= ATT_SCALE;
            }
        }

        // ---- online softmax ----
        float mn0 = m0, mn1 = m1;
#pragma unroll
        for (int j = 0; j < 16; j++) {
            mn0 = fmaxf(mn0, fmaxf(sfr[j][0], sfr[j][1]));
            mn1 = fmaxf(mn1, fmaxf(sfr[j][2], sfr[j][3]));
        }
        mn0 = fmaxf(mn0, __shfl_xor_sync(0xffffffffu, mn0, 1));
        mn0 = fmaxf(mn0, __shfl_xor_sync(0xffffffffu, mn0, 2));
        mn1 = fmaxf(mn1, __shfl_xor_sync(0xffffffffu, mn1, 1));
        mn1 = fmaxf(mn1, __shfl_xor_sync(0xffffffffu, mn1, 2));

        const float alpha0 = __expf(m0 - mn0);
        const float alpha1 = __expf(m1 - mn1);
        m0 = mn0; m1 = mn1;

        float sum0 = 0.f, sum1 = 0.f;
#pragma unroll
        for (int j = 0; j < 16; j++) {
            sfr[j][0] = __expf(sfr[j][0] - mn0);
            sfr[j][1] = __expf(sfr[j][1] - mn0);
            sfr[j][2] = __expf(sfr[j][2] - mn1);
            sfr[j][3] = __expf(sfr[j][3] - mn1);
            sum0 += sfr[j][0] + sfr[j][1];
            sum1 += sfr[j][2] + sfr[j][3];
        }
        sum0 += __shfl_xor_sync(0xffffffffu, sum0, 1);
        sum0 += __shfl_xor_sync(0xffffffffu, sum0, 2);
        sum1 += __shfl_xor_sync(0xffffffffu, sum1, 1);
        sum1 += __shfl_xor_sync(0xffffffffu, sum1, 2);
        l0 = l0 * alpha0 + sum0;
        l1 = l1 * alpha1 + sum1;

#pragma unroll
        for (int j = 0; j < 8; j++) {
            ofr[j][0] *= alpha0; ofr[j][1] *= alpha0;
            ofr[j][2] *= alpha1; ofr[j][3] *= alpha1;
        }

        // ---- O += Ph·Vh : 1-pass (P rounded) ----
#pragma unroll
        for (int u = 0; u < 8; u++) {
            uint32_t aPh[4];
            aPh[0] = pack_h(sfr[2*u][0],   sfr[2*u][1]);
            aPh[1] = pack_h(sfr[2*u][2],   sfr[2*u][3]);
            aPh[2] = pack_h(sfr[2*u+1][0], sfr[2*u+1][1]);
            aPh[3] = pack_h(sfr[2*u+1][2], sfr[2*u+1][3]);
#pragma unroll
            for (int cc = 0; cc < 4; cc++) {
                uint32_t bVh[4];
                const uint32_t voff =
                    (uint32_t)(((16 * u + lr) * ALD + 16 * cc + lc8) * 2);
                ldsm_x4_t(bVh, uVh + voff);
                mma_f16(ofr[2*cc],     aPh, bVh);
                mma_f16(ofr[2*cc + 1], aPh, bVh + 2);
            }
        }
    }

    // ---- epilogue: normalize, split fp16 hi/lo, store ----
    const float inv0 = 1.f / l0, inv1 = 1.f / l1;
    const int row0 = q0 + wid * 16 + g, row1 = row0 + 8;
#pragma unroll
    for (int j = 0; j < 8; j++) {
        const int c = h * HEAD_DIM + 8 * j + 2 * t;
        uint32_t hv, lv;
        split_pack_h(ofr[j][0] * inv0, ofr[j][1] * inv0, hv, lv);
        *(uint32_t*)(oh + (size_t)row0 * D_MODEL + c) = hv;
        *(uint32_t*)(ol + (size_t)row0 * D_MODEL + c) = lv;
        split_pack_h(ofr[j][2] * inv1, ofr[j][3] * inv1, hv, lv);
        *(uint32_t*)(oh + (size_t)row1 * D_MODEL + c) = hv;
        *(uint32_t*)(ol + (size_t)row1 * D_MODEL + c) = lv;
    }
}

// ---------------------------------------------------------------------------
extern "C" void kernel_launch(void* const* d_in, const int* in_sizes, int n_in,
                              void* d_out, int out_size)
{
    const float* x     = (const float*)d_in[0];
    const float* w_qkv = (const float*)d_in[1];
    const float* b_qkv = (const float*)d_in[2];
    const float* w_out = (const float*)d_in[3];
    const float* b_out = (const float*)d_in[4];
    float* out = (float*)d_out;

    __half *xh, *xl, *qkv, *ah, *al, *wqh, *woh;
    cudaGetSymbolAddress((void**)&xh, g_xh);
    cudaGetSymbolAddress((void**)&xl, g_xl);
    cudaGetSymbolAddress((void**)&qkv, g_qkv);
    cudaGetSymbolAddress((void**)&ah, g_ah);
    cudaGetSymbolAddress((void**)&al, g_al);
    cudaGetSymbolAddress((void**)&wqh, g_wqh);
    cudaGetSymbolAddress((void**)&woh, g_woh);

    cudaFuncSetAttribute(gemm_mma_kernel,
                         cudaFuncAttributeMaxDynamicSharedMemorySize, GEMM_SMEM);
    cudaFuncSetAttribute(flash_attn_mma_kernel,
                         cudaFuncAttributeMaxDynamicSharedMemorySize, FA_SMEM);

    {
        const int nx = S_LEN * D_MODEL;
        split_rows_kernel<<<nx / (256 * 4), 256>>>(x, xh, xl, nx);
        dim3 g1(QKV_COLS / 32, D_MODEL / 32), b1(32, 8);
        transpose_round_kernel<<<g1, b1>>>(w_qkv, wqh, D_MODEL, QKV_COLS);
        dim3 g2(D_MODEL / 32, D_MODEL / 32);
        transpose_round_kernel<<<g2, b1>>>(w_out, woh, D_MODEL, D_MODEL);
    }

    // 1) qkv (fp16) = (xh+xl) @ wqh + b_qkv
    {
        dim3 grid(QKV_COLS / 128, S_LEN / 128);
        gemm_mma_kernel<<<grid, 256, GEMM_SMEM>>>(xh, xl, wqh, b_qkv,
                                                  nullptr, qkv, nullptr, 2,
                                                  S_LEN, QKV_COLS, D_MODEL);
    }
    // 2) attention -> ah/al (fp16 hi/lo)
    {
        dim3 grid(S_LEN / 128, N_HEADS);
        flash_attn_mma_kernel<<<grid, 256, FA_SMEM>>>(qkv, ah, al);
    }
    // 3) out = (ah+al) @ woh + b_out (fp32)
    {
        dim3 grid(D_MODEL / 128, S_LEN / 128);
        gemm_mma_kernel<<<grid, 256, GEMM_SMEM>>>(ah, al, woh, b_out,
                                                  out, nullptr, nullptr, 0,
                                                  S_LEN, D_MODEL, D_MODEL);
    }
}

// round 15
// speedup vs baseline: 1.9727x; 1.1601x over previous
#include <cuda_runtime.h>
#include <cuda_fp16.h>
#include <cstdint>
#include <math.h>

#define S_LEN    4096
#define D_MODEL  1024
#define QKV_COLS 3072
#define N_HEADS  16
#define HEAD_DIM 64
#define ATT_SCALE 0.125f

// ---------------- scratch (__device__ globals; no cudaMalloc) ----------------
static __device__ __align__(256) __half g_xh[S_LEN * D_MODEL];
static __device__ __align__(256) __half g_qkv[S_LEN * QKV_COLS];   // fp16 qkv
static __device__ __align__(256) __half g_ah[S_LEN * D_MODEL];
static __device__ __align__(256) __half g_al[S_LEN * D_MODEL];
static __device__ __align__(256) __half g_wqh[QKV_COLS * D_MODEL]; // [N][K] fp16
static __device__ __align__(256) __half g_woh[D_MODEL * D_MODEL];

// ---------------- PTX helpers ----------------
__device__ __forceinline__ uint32_t smem_u32(const void* p) {
    uint32_t a;
    asm("{ .reg .u64 t; cvta.to.shared.u64 t, %1; cvt.u32.u64 %0, t; }"
        : "=r"(a) : "l"(p));
    return a;
}
__device__ __forceinline__ void cp_async16(uint32_t saddr, const void* gptr) {
    asm volatile("cp.async.cg.shared.global [%0], [%1], 16;"
                 :: "r"(saddr), "l"(gptr));
}
#define CP_COMMIT() asm volatile("cp.async.commit_group;" ::: "memory")
#define CP_WAIT(n)  asm volatile("cp.async.wait_group %0;" :: "n"(n) : "memory")

__device__ __forceinline__ void ldsm_x4(uint32_t* r, uint32_t addr) {
    asm volatile("ldmatrix.sync.aligned.m8n8.x4.shared.b16 {%0,%1,%2,%3}, [%4];"
                 : "=r"(r[0]), "=r"(r[1]), "=r"(r[2]), "=r"(r[3]) : "r"(addr));
}
__device__ __forceinline__ void ldsm_x4_t(uint32_t* r, uint32_t addr) {
    asm volatile("ldmatrix.sync.aligned.m8n8.x4.trans.shared.b16 {%0,%1,%2,%3}, [%4];"
                 : "=r"(r[0]), "=r"(r[1]), "=r"(r[2]), "=r"(r[3]) : "r"(addr));
}
__device__ __forceinline__ void mma_f16(float* c, const uint32_t* a, const uint32_t* b) {
    asm volatile("mma.sync.aligned.m16n8k16.row.col.f32.f16.f16.f32 "
                 "{%0,%1,%2,%3}, {%4,%5,%6,%7}, {%8,%9}, {%0,%1,%2,%3};"
                 : "+f"(c[0]), "+f"(c[1]), "+f"(c[2]), "+f"(c[3])
                 : "r"(a[0]), "r"(a[1]), "r"(a[2]), "r"(a[3]), "r"(b[0]), "r"(b[1]));
}
__device__ __forceinline__ void split_pack_h(float x, float y, uint32_t& hi, uint32_t& lo) {
    __half hx = __float2half_rn(x), hy = __float2half_rn(y);
    __half lx = __float2half_rn(x - __half2float(hx));
    __half ly = __float2half_rn(y - __half2float(hy));
    hi = ((uint32_t)__half_as_ushort(hy) << 16) | __half_as_ushort(hx);
    lo = ((uint32_t)__half_as_ushort(ly) << 16) | __half_as_ushort(lx);
}
__device__ __forceinline__ uint32_t pack_h(float x, float y) {
    __half hx = __float2half_rn(x), hy = __float2half_rn(y);
    return ((uint32_t)__half_as_ushort(hy) << 16) | __half_as_ushort(hx);
}

// ---------------- convert kernels ----------------
__global__ void round_rows_kernel(const float* __restrict__ src,
                                  __half* __restrict__ hi, int n)
{
    int i = (blockIdx.x * blockDim.x + threadIdx.x) * 4;
    if (i >= n) return;
    float4 v = *(const float4*)(src + i);
    uint32_t h0 = pack_h(v.x, v.y);
    uint32_t h1 = pack_h(v.z, v.w);
    *(uint2*)(hi + i) = make_uint2(h0, h1);
}

__global__ void transpose_round_kernel(const float* __restrict__ w,
                                       __half* __restrict__ hi,
                                       int K, int N)
{
    __shared__ float tile[32][33];
    const int n0 = blockIdx.x * 32, k0 = blockIdx.y * 32;
    const int tx = threadIdx.x, ty = threadIdx.y;   // 32 x 8
#pragma unroll
    for (int i = 0; i < 4; i++)
        tile[ty + 8 * i][tx] = w[(size_t)(k0 + ty + 8 * i) * N + n0 + tx];
    __syncthreads();
#pragma unroll
    for (int i = 0; i < 4; i++) {
        const int r = ty + 8 * i;
        hi[(size_t)(n0 + r) * K + k0 + tx] = __float2half_rn(tile[tx][r]);
    }
}

// ---- raw mma.sync fp16 GEMM: C = (Ah [+Al])·Bh^T + bias --------------------
// APASS: 1 = A rounded (skip Al), 2 = A split hi/lo (exact A).
// hilo: 0 = fp32 out, 2 = fp16 (rounded) out
#define GLD 40
#define GTILE  (128 * GLD * 2)            // 10240 B per array
#define GSTAGE (3 * GTILE)                // 30720 B per stage (Ah, Al, Bh slots)
#define GEMM_SMEM (128 * 132 * 4)         // 67584 B (epilogue dominates; stages alias)

template<int APASS>
__global__ __launch_bounds__(256, 2)      // force <=128 regs -> 2 CTAs/SM
void gemm_mma_kernel(const __half* __restrict__ Ah,
                     const __half* __restrict__ Al,
                     const __half* __restrict__ Bh,
                     const float* __restrict__ bias,
                     float* __restrict__ Cf,
                     __half* __restrict__ Ch,
                     int hilo, int M, int N, int K)
{
    extern __shared__ char smraw[];
    float* Cs = (float*)smraw;
    const uint32_t sb = smem_u32(smraw);

    const int tid = threadIdx.x;
    const int wid = tid >> 5;
    const int lane = tid & 31;
    const int wr = wid >> 1;
    const int wc = wid & 1;
    const int g  = lane >> 2;
    const int t  = lane & 3;
    const int lr = lane & 15;
    const int lc8 = (lane >> 4) * 8;
    const int kk = (lane & 7) + ((lane & 16) >> 1);
    const int kd8 = lane & 8;
    const int m0 = blockIdx.y * 128, n0 = blockIdx.x * 128;

    float acc[16][4];
#pragma unroll
    for (int q = 0; q < 16; q++)
#pragma unroll
        for (int e = 0; e < 4; e++) acc[q][e] = 0.f;

    int crow[2], cbyte[2];
#pragma unroll
    for (int i = 0; i < 2; i++) {
        const int idx = tid + i * 256;
        crow[i]  = idx >> 2;
        cbyte[i] = (idx & 3) * 16;
    }

    const int NT = K / 32;

    // prefetch stage 0
#pragma unroll
    for (int i = 0; i < 2; i++) {
        const int r = crow[i];
        const int gcol = cbyte[i] / 2;
        const uint32_t so = (uint32_t)(r * GLD * 2 + cbyte[i]);
        cp_async16(sb + so, Ah + (size_t)(m0 + r) * K + gcol);
        if (APASS == 2)
            cp_async16(sb + GTILE + so, Al + (size_t)(m0 + r) * K + gcol);
        cp_async16(sb + 2 * GTILE + so, Bh + (size_t)(n0 + r) * K + gcol);
    }
    CP_COMMIT();

    for (int kt = 0; kt < NT; kt++) {
        __syncthreads();
        if (kt + 1 < NT) {
            const int k1 = (kt + 1) * 32;
            const uint32_t st = sb + ((kt + 1) & 1) * GSTAGE;
#pragma unroll
            for (int i = 0; i < 2; i++) {
                const int r = crow[i];
                const int gcol = k1 + cbyte[i] / 2;
                const uint32_t so = (uint32_t)(r * GLD * 2 + cbyte[i]);
                cp_async16(st + so, Ah + (size_t)(m0 + r) * K + gcol);
                if (APASS == 2)
                    cp_async16(st + GTILE + so, Al + (size_t)(m0 + r) * K + gcol);
                cp_async16(st + 2 * GTILE + so, Bh + (size_t)(n0 + r) * K + gcol);
            }
            CP_COMMIT();
            CP_WAIT(1);
        } else {
            CP_WAIT(0);
        }
        __syncthreads();

        const uint32_t uAh = sb + (kt & 1) * GSTAGE;
        const uint32_t uAl = uAh + GTILE;
        const uint32_t uBh = uAh + 2 * GTILE;

#pragma unroll
        for (int sub = 0; sub < 2; sub++) {
            const int kc = sub * 16;
            uint32_t ah[2][4], al[2][4];
#pragma unroll
            for (int i = 0; i < 2; i++) {
                const uint32_t aoff =
                    (uint32_t)(((wr * 32 + i * 16 + lr) * GLD + kc + lc8) * 2);
                ldsm_x4(ah[i], uAh + aoff);
                if (APASS == 2) ldsm_x4(al[i], uAl + aoff);
            }
#pragma unroll
            for (int jj = 0; jj < 4; jj++) {
                uint32_t bh[4];
                const uint32_t boff =
                    (uint32_t)(((wc * 64 + jj * 16 + kk) * GLD + kc + kd8) * 2);
                ldsm_x4(bh, uBh + boff);
#pragma unroll
                for (int i = 0; i < 2; i++) {
                    float* c0 = acc[i * 8 + 2 * jj];
                    float* c1 = acc[i * 8 + 2 * jj + 1];
                    mma_f16(c0, ah[i], bh);
                    if (APASS == 2) mma_f16(c0, al[i], bh);
                    mma_f16(c1, ah[i], bh + 2);
                    if (APASS == 2) mma_f16(c1, al[i], bh + 2);
                }
            }
        }
    }

    __syncthreads();
#pragma unroll
    for (int i = 0; i < 2; i++)
#pragma unroll
        for (int f = 0; f < 8; f++) {
            const int row = wr * 32 + i * 16 + g;
            const int col = wc * 64 + 8 * f + 2 * t;
            const float* c = acc[i * 8 + f];
            *(float2*)&Cs[row * 132 + col]       = make_float2(c[0], c[1]);
            *(float2*)&Cs[(row + 8) * 132 + col] = make_float2(c[2], c[3]);
        }
    __syncthreads();

    {
        const int r = tid >> 1;
        const int cb = (tid & 1) * 64;
        const float* bp = bias + n0 + cb;
        const float* sp = &Cs[r * 132 + cb];
        if (hilo == 0) {
            float* cp = Cf + (size_t)(m0 + r) * N + n0 + cb;
#pragma unroll
            for (int j = 0; j < 64; j += 4) {
                float4 o;
                o.x = sp[j+0] + bp[j+0]; o.y = sp[j+1] + bp[j+1];
                o.z = sp[j+2] + bp[j+2]; o.w = sp[j+3] + bp[j+3];
                *(float4*)(cp + j) = o;
            }
        } else {
            __half* hp = Ch + (size_t)(m0 + r) * N + n0 + cb;
#pragma unroll
            for (int j = 0; j < 64; j += 4) {
                uint32_t h0 = pack_h(sp[j+0] + bp[j+0], sp[j+1] + bp[j+1]);
                uint32_t h1 = pack_h(sp[j+2] + bp[j+2], sp[j+3] + bp[j+3]);
                *(uint2*)(hp + j) = make_uint2(h0, h1);
            }
        }
    }
}

// ---------------------------------------------------------------------------
// Flash attention fp16, 1-pass QK and PV (identical to R14 version).
// ---------------------------------------------------------------------------
#define ALD 72                              // fp16 elems per smem row
#define FARR (128 * ALD * 2)                // 18432 B per array
#define FA_KVSTAGE (2 * FARR)               // Kh Vh = 36864 B
#define FA_KVBASE  FARR                     // after Qh
#define FA_SMEM (FA_KVBASE + 2 * FA_KVSTAGE)  // 92160 B

__global__ __launch_bounds__(256, 1)
void flash_attn_mma_kernel(const __half* __restrict__ qkv,
                           __half* __restrict__ oh,
                           __half* __restrict__ ol)
{
    extern __shared__ char smraw[];
    __half* sQh = (__half*)smraw;
    const uint32_t sb = smem_u32(smraw);

    const int qb  = gridDim.x - 1 - blockIdx.x;   // long rows first
    const int h   = blockIdx.y;
    const int tid = threadIdx.x;
    const int wid = tid >> 5;
    const int lane = tid & 31;
    const int q0  = qb * 128;

    const int g  = lane >> 2;
    const int t  = lane & 3;
    const int lr = lane & 15;
    const int lc8 = (lane >> 4) * 8;
    const int kk = (lane & 7) + ((lane & 16) >> 1);
    const int kd8 = lane & 8;

    const int colK = D_MODEL + h * HEAD_DIM;
    const int colV = 2 * D_MODEL + h * HEAD_DIM;

    int crow[4], cbyte[4];
#pragma unroll
    for (int i = 0; i < 4; i++) {
        const int idx = tid + i * 256;
        crow[i]  = idx >> 3;
        cbyte[i] = (idx & 7) * 16;
    }

    // ---- load Q tile ----
#pragma unroll
    for (int i = 0; i < 4; i++) {
        const int r = crow[i], c = cbyte[i] / 2;
        const size_t gofs = (size_t)(q0 + r) * QKV_COLS + h * HEAD_DIM + c;
        *(uint4*)(sQh + r * ALD + c) = *(const uint4*)(qkv + gofs);
    }

    // ---- prefetch K/V stage 0 ----
    {
        const uint32_t st = sb + FA_KVBASE;
#pragma unroll
        for (int i = 0; i < 4; i++) {
            const int r = crow[i];
            const uint32_t so = (uint32_t)(r * ALD * 2 + cbyte[i]);
            const size_t gr = (size_t)r * QKV_COLS;
            const int c = cbyte[i] / 2;
            cp_async16(st + so,        qkv + gr + colK + c);
            cp_async16(st + FARR + so, qkv + gr + colV + c);
        }
        CP_COMMIT();
    }

    float ofr[8][4];
    float m0 = -1e30f, m1 = -1e30f, l0 = 0.f, l1 = 0.f;
#pragma unroll
    for (int j = 0; j < 8; j++)
#pragma unroll
        for (int e = 0; e < 4; e++) ofr[j][e] = 0.f;

    for (int kt = 0; kt <= qb; kt++) {
        __syncthreads();
        if (kt + 1 <= qb) {
            const int k1 = (kt + 1) * 128;
            const uint32_t st = sb + FA_KVBASE + ((kt + 1) & 1) * FA_KVSTAGE;
#pragma unroll
            for (int i = 0; i < 4; i++) {
                const int r = crow[i];
                const uint32_t so = (uint32_t)(r * ALD * 2 + cbyte[i]);
                const size_t gr = (size_t)(k1 + r) * QKV_COLS;
                const int c = cbyte[i] / 2;
                cp_async16(st + so,        qkv + gr + colK + c);
                cp_async16(st + FARR + so, qkv + gr + colV + c);
            }
            CP_COMMIT();
            CP_WAIT(1);
        } else {
            CP_WAIT(0);
        }
        __syncthreads();

        const uint32_t stg = sb + FA_KVBASE + (kt & 1) * FA_KVSTAGE;
        const uint32_t uKh = stg, uVh = stg + FARR;
        const uint32_t uQh = sb;

        // ---- S = Qh·Kh^T ----
        float sfr[16][4];
#pragma unroll
        for (int j = 0; j < 16; j++)
#pragma unroll
            for (int e = 0; e < 4; e++) sfr[j][e] = 0.f;

#pragma unroll
        for (int u = 0; u < 4; u++) {
            uint32_t aQh[4];
            const uint32_t qoff =
                (uint32_t)(((wid * 16 + lr) * ALD + 16 * u + lc8) * 2);
            ldsm_x4(aQh, uQh + qoff);
#pragma unroll
            for (int jj = 0; jj < 8; jj++) {
                uint32_t bKh[4];
                const uint32_t koff =
                    (uint32_t)(((16 * jj + kk) * ALD + 16 * u + kd8) * 2);
                ldsm_x4(bKh, uKh + koff);
                mma_f16(sfr[2*jj],   aQh, bKh);
                mma_f16(sfr[2*jj+1], aQh, bKh + 2);
            }
        }

        // ---- scale + causal mask ----
        if (kt == qb) {
            const int gq0 = wid * 16 + g, gq1 = gq0 + 8;
#pragma unroll
            for (int j = 0; j < 16; j++) {
                const int c = 8 * j + 2 * t;
                sfr[j][0] = (c     <= gq0) ? sfr[j][0] * ATT_SCALE : -1e30f;
                sfr[j][1] = (c + 1 <= gq0) ? sfr[j][1] * ATT_SCALE : -1e30f;
                sfr[j][2] = (c     <= gq1) ? sfr[j][2] * ATT_SCALE : -1e30f;
                sfr[j][3] = (c + 1 <= gq1) ? sfr[j][3] * ATT_SCALE : -1e30f;
            }
        } else {
#pragma unroll
            for (int j = 0; j < 16; j++) {
                sfr[j][0] *= ATT_SCALE; sfr[j][1] *= ATT_SCALE;
                sfr[j][2] *= ATT_SCALE; sfr[j][3] *= ATT_SCALE;
            }
        }

        // ---- online softmax ----
        float mn0 = m0, mn1 = m1;
#pragma unroll
        for (int j = 0; j < 16; j++) {
            mn0 = fmaxf(mn0, fmaxf(sfr[j][0], sfr[j][1]));
            mn1 = fmaxf(mn1, fmaxf(sfr[j][2], sfr[j][3]));
        }
        mn0 = fmaxf(mn0, __shfl_xor_sync(0xffffffffu, mn0, 1));
        mn0 = fmaxf(mn0, __shfl_xor_sync(0xffffffffu, mn0, 2));
        mn1 = fmaxf(mn1, __shfl_xor_sync(0xffffffffu, mn1, 1));
        mn1 = fmaxf(mn1, __shfl_xor_sync(0xffffffffu, mn1, 2));

        const float alpha0 = __expf(m0 - mn0);
        const float alpha1 = __expf(m1 - mn1);
        m0 = mn0; m1 = mn1;

        float sum0 = 0.f, sum1 = 0.f;
#pragma unroll
        for (int j = 0; j < 16; j++) {
            sfr[j][0] = __expf(sfr[j][0] - mn0);
            sfr[j][1] = __expf(sfr[j][1] - mn0);
            sfr[j][2] = __expf(sfr[j][2] - mn1);
            sfr[j][3] = __expf(sfr[j][3] - mn1);
            sum0 += sfr[j][0] + sfr[j][1];
            sum1 += sfr[j][2] + sfr[j][3];
        }
        sum0 += __shfl_xor_sync(0xffffffffu, sum0, 1);
        sum0 += __shfl_xor_sync(0xffffffffu, sum0, 2);
        sum1 += __shfl_xor_sync(0xffffffffu, sum1, 1);
        sum1 += __shfl_xor_sync(0xffffffffu, sum1, 2);
        l0 = l0 * alpha0 + sum0;
        l1 = l1 * alpha1 + sum1;

#pragma unroll
        for (int j = 0; j < 8; j++) {
            ofr[j][0] *= alpha0; ofr[j][1] *= alpha0;
            ofr[j][2] *= alpha1; ofr[j][3] *= alpha1;
        }

        // ---- O += Ph·Vh ----
#pragma unroll
        for (int u = 0; u < 8; u++) {
            uint32_t aPh[4];
            aPh[0] = pack_h(sfr[2*u][0],   sfr[2*u][1]);
            aPh[1] = pack_h(sfr[2*u][2],   sfr[2*u][3]);
            aPh[2] = pack_h(sfr[2*u+1][0], sfr[2*u+1][1]);
            aPh[3] = pack_h(sfr[2*u+1][2], sfr[2*u+1][3]);
#pragma unroll
            for (int cc = 0; cc < 4; cc++) {
                uint32_t bVh[4];
                const uint32_t voff =
                    (uint32_t)(((16 * u + lr) * ALD + 16 * cc + lc8) * 2);
                ldsm_x4_t(bVh, uVh + voff);
                mma_f16(ofr[2*cc],     aPh, bVh);
                mma_f16(ofr[2*cc + 1], aPh, bVh + 2);
            }
        }
    }

    // ---- epilogue ----
    const float inv0 = 1.f / l0, inv1 = 1.f / l1;
    const int row0 = q0 + wid * 16 + g, row1 = row0 + 8;
#pragma unroll
    for (int j = 0; j < 8; j++) {
        const int c = h * HEAD_DIM + 8 * j + 2 * t;
        uint32_t hv, lv;
        split_pack_h(ofr[j][0] * inv0, ofr[j][1] * inv0, hv, lv);
        *(uint32_t*)(oh + (size_t)row0 * D_MODEL + c) = hv;
        *(uint32_t*)(ol + (size_t)row0 * D_MODEL + c) = lv;
        split_pack_h(ofr[j][2] * inv1, ofr[j][3] * inv1, hv, lv);
        *(uint32_t*)(oh + (size_t)row1 * D_MODEL + c) = hv;
        *(uint32_t*)(ol + (size_t)row1 * D_MODEL + c) = lv;
    }
}

// ---------------------------------------------------------------------------
extern "C" void kernel_launch(void* const* d_in, const int* in_sizes, int n_in,
                              void* d_out, int out_size)
{
    const float* x     = (const float*)d_in[0];
    const float* w_qkv = (const float*)d_in[1];
    const float* b_qkv = (const float*)d_in[2];
    const float* w_out = (const float*)d_in[3];
    const float* b_out = (const float*)d_in[4];
    float* out = (float*)d_out;

    __half *xh, *qkv, *ah, *al, *wqh, *woh;
    cudaGetSymbolAddress((void**)&xh, g_xh);
    cudaGetSymbolAddress((void**)&qkv, g_qkv);
    cudaGetSymbolAddress((void**)&ah, g_ah);
    cudaGetSymbolAddress((void**)&al, g_al);
    cudaGetSymbolAddress((void**)&wqh, g_wqh);
    cudaGetSymbolAddress((void**)&woh, g_woh);

    cudaFuncSetAttribute(gemm_mma_kernel<1>,
                         cudaFuncAttributeMaxDynamicSharedMemorySize, GEMM_SMEM);
    cudaFuncSetAttribute(gemm_mma_kernel<2>,
                         cudaFuncAttributeMaxDynamicSharedMemorySize, GEMM_SMEM);
    cudaFuncSetAttribute(flash_attn_mma_kernel,
                         cudaFuncAttributeMaxDynamicSharedMemorySize, FA_SMEM);

    {
        const int nx = S_LEN * D_MODEL;
        round_rows_kernel<<<nx / (256 * 4), 256>>>(x, xh, nx);
        dim3 g1(QKV_COLS / 32, D_MODEL / 32), b1(32, 8);
        transpose_round_kernel<<<g1, b1>>>(w_qkv, wqh, D_MODEL, QKV_COLS);
        dim3 g2(D_MODEL / 32, D_MODEL / 32);
        transpose_round_kernel<<<g2, b1>>>(w_out, woh, D_MODEL, D_MODEL);
    }

    // 1) qkv (fp16) = xh @ wqh + b_qkv   (1-pass)
    {
        dim3 grid(QKV_COLS / 128, S_LEN / 128);
        gemm_mma_kernel<1><<<grid, 256, GEMM_SMEM>>>(xh, nullptr, wqh, b_qkv,
                                                     nullptr, qkv, 2,
                                                     S_LEN, QKV_COLS, D_MODEL);
    }
    // 2) attention -> ah/al (fp16 hi/lo)
    {
        dim3 grid(S_LEN / 128, N_HEADS);
        flash_attn_mma_kernel<<<grid, 256, FA_SMEM>>>(qkv, ah, al);
    }
    // 3) out = (ah+al) @ woh + b_out (fp32, 2-pass)
    {
        dim3 grid(D_MODEL / 128, S_LEN / 128);
        gemm_mma_kernel<2><<<grid, 256, GEMM_SMEM>>>(ah, al, woh, b_out,
                                                     out, nullptr, 0,
                                                     S_LEN, D_MODEL, D_MODEL);
    }
}

// round 16
// speedup vs baseline: 2.0636x; 1.0461x over previous
#include <cuda_runtime.h>
#include <cuda_fp16.h>
#include <cstdint>
#include <math.h>

#define S_LEN    4096
#define D_MODEL  1024
#define QKV_COLS 3072
#define N_HEADS  16
#define HEAD_DIM 64
#define ATT_SCALE 0.125f

// ---------------- scratch (__device__ globals; no cudaMalloc) ----------------
static __device__ __align__(256) __half g_xh[S_LEN * D_MODEL];
static __device__ __align__(256) __half g_qkv[S_LEN * QKV_COLS];   // fp16 qkv
static __device__ __align__(256) __half g_ah[S_LEN * D_MODEL];
static __device__ __align__(256) __half g_wqh[QKV_COLS * D_MODEL]; // [N][K] fp16
static __device__ __align__(256) __half g_woh[D_MODEL * D_MODEL];

// ---------------- PTX helpers ----------------
__device__ __forceinline__ uint32_t smem_u32(const void* p) {
    uint32_t a;
    asm("{ .reg .u64 t; cvta.to.shared.u64 t, %1; cvt.u32.u64 %0, t; }"
        : "=r"(a) : "l"(p));
    return a;
}
__device__ __forceinline__ void cp_async16(uint32_t saddr, const void* gptr) {
    asm volatile("cp.async.cg.shared.global [%0], [%1], 16;"
                 :: "r"(saddr), "l"(gptr));
}
#define CP_COMMIT() asm volatile("cp.async.commit_group;" ::: "memory")
#define CP_WAIT(n)  asm volatile("cp.async.wait_group %0;" :: "n"(n) : "memory")

__device__ __forceinline__ void ldsm_x4(uint32_t* r, uint32_t addr) {
    asm volatile("ldmatrix.sync.aligned.m8n8.x4.shared.b16 {%0,%1,%2,%3}, [%4];"
                 : "=r"(r[0]), "=r"(r[1]), "=r"(r[2]), "=r"(r[3]) : "r"(addr));
}
__device__ __forceinline__ void ldsm_x4_t(uint32_t* r, uint32_t addr) {
    asm volatile("ldmatrix.sync.aligned.m8n8.x4.trans.shared.b16 {%0,%1,%2,%3}, [%4];"
                 : "=r"(r[0]), "=r"(r[1]), "=r"(r[2]), "=r"(r[3]) : "r"(addr));
}
__device__ __forceinline__ void mma_f16(float* c, const uint32_t* a, const uint32_t* b) {
    asm volatile("mma.sync.aligned.m16n8k16.row.col.f32.f16.f16.f32 "
                 "{%0,%1,%2,%3}, {%4,%5,%6,%7}, {%8,%9}, {%0,%1,%2,%3};"
                 : "+f"(c[0]), "+f"(c[1]), "+f"(c[2]), "+f"(c[3])
                 : "r"(a[0]), "r"(a[1]), "r"(a[2]), "r"(a[3]), "r"(b[0]), "r"(b[1]));
}
__device__ __forceinline__ uint32_t pack_h(float x, float y) {
    __half hx = __float2half_rn(x), hy = __float2half_rn(y);
    return ((uint32_t)__half_as_ushort(hy) << 16) | __half_as_ushort(hx);
}

// ---------------- convert kernels ----------------
__global__ void round_rows_kernel(const float* __restrict__ src,
                                  __half* __restrict__ hi, int n)
{
    int i = (blockIdx.x * blockDim.x + threadIdx.x) * 4;
    if (i >= n) return;
    float4 v = *(const float4*)(src + i);
    uint32_t h0 = pack_h(v.x, v.y);
    uint32_t h1 = pack_h(v.z, v.w);
    *(uint2*)(hi + i) = make_uint2(h0, h1);
}

__global__ void transpose_round_kernel(const float* __restrict__ w,
                                       __half* __restrict__ hi,
                                       int K, int N)
{
    __shared__ float tile[32][33];
    const int n0 = blockIdx.x * 32, k0 = blockIdx.y * 32;
    const int tx = threadIdx.x, ty = threadIdx.y;   // 32 x 8
#pragma unroll
    for (int i = 0; i < 4; i++)
        tile[ty + 8 * i][tx] = w[(size_t)(k0 + ty + 8 * i) * N + n0 + tx];
    __syncthreads();
#pragma unroll
    for (int i = 0; i < 4; i++) {
        const int r = ty + 8 * i;
        hi[(size_t)(n0 + r) * K + k0 + tx] = __float2half_rn(tile[tx][r]);
    }
}

// ---- raw mma.sync fp16 1-pass GEMM: C = Ah·Bh^T + bias ---------------------
// hilo: 0 = fp32 out, 2 = fp16 (rounded) out
#define GLD 40
#define GTILE  (128 * GLD * 2)            // 10240 B per array
#define GSTAGE (2 * GTILE)                // 20480 B per stage (Ah, Bh)
#define GEMM_SMEM (128 * 132 * 4)         // 67584 B (epilogue dominates; stages alias)

__global__ __launch_bounds__(256, 2)      // force <=128 regs -> 2 CTAs/SM
void gemm_mma_kernel(const __half* __restrict__ Ah,
                     const __half* __restrict__ Bh,
                     const float* __restrict__ bias,
                     float* __restrict__ Cf,
                     __half* __restrict__ Ch,
                     int hilo, int M, int N, int K)
{
    extern __shared__ char smraw[];
    float* Cs = (float*)smraw;
    const uint32_t sb = smem_u32(smraw);

    const int tid = threadIdx.x;
    const int wid = tid >> 5;
    const int lane = tid & 31;
    const int wr = wid >> 1;
    const int wc = wid & 1;
    const int g  = lane >> 2;
    const int t  = lane & 3;
    const int lr = lane & 15;
    const int lc8 = (lane >> 4) * 8;
    const int kk = (lane & 7) + ((lane & 16) >> 1);
    const int kd8 = lane & 8;
    const int m0 = blockIdx.y * 128, n0 = blockIdx.x * 128;

    float acc[16][4];
#pragma unroll
    for (int q = 0; q < 16; q++)
#pragma unroll
        for (int e = 0; e < 4; e++) acc[q][e] = 0.f;

    int crow[2], cbyte[2];
#pragma unroll
    for (int i = 0; i < 2; i++) {
        const int idx = tid + i * 256;
        crow[i]  = idx >> 2;
        cbyte[i] = (idx & 3) * 16;
    }

    const int NT = K / 32;

    // prefetch stage 0
#pragma unroll
    for (int i = 0; i < 2; i++) {
        const int r = crow[i];
        const int gcol = cbyte[i] / 2;
        const uint32_t so = (uint32_t)(r * GLD * 2 + cbyte[i]);
        cp_async16(sb + so,         Ah + (size_t)(m0 + r) * K + gcol);
        cp_async16(sb + GTILE + so, Bh + (size_t)(n0 + r) * K + gcol);
    }
    CP_COMMIT();

    for (int kt = 0; kt < NT; kt++) {
        __syncthreads();
        if (kt + 1 < NT) {
            const int k1 = (kt + 1) * 32;
            const uint32_t st = sb + ((kt + 1) & 1) * GSTAGE;
#pragma unroll
            for (int i = 0; i < 2; i++) {
                const int r = crow[i];
                const int gcol = k1 + cbyte[i] / 2;
                const uint32_t so = (uint32_t)(r * GLD * 2 + cbyte[i]);
                cp_async16(st + so,         Ah + (size_t)(m0 + r) * K + gcol);
                cp_async16(st + GTILE + so, Bh + (size_t)(n0 + r) * K + gcol);
            }
            CP_COMMIT();
            CP_WAIT(1);
        } else {
            CP_WAIT(0);
        }
        __syncthreads();

        const uint32_t uAh = sb + (kt & 1) * GSTAGE;
        const uint32_t uBh = uAh + GTILE;

#pragma unroll
        for (int sub = 0; sub < 2; sub++) {
            const int kc = sub * 16;
            uint32_t ah[2][4];
#pragma unroll
            for (int i = 0; i < 2; i++) {
                const uint32_t aoff =
                    (uint32_t)(((wr * 32 + i * 16 + lr) * GLD + kc + lc8) * 2);
                ldsm_x4(ah[i], uAh + aoff);
            }
#pragma unroll
            for (int jj = 0; jj < 4; jj++) {
                uint32_t bh[4];
                const uint32_t boff =
                    (uint32_t)(((wc * 64 + jj * 16 + kk) * GLD + kc + kd8) * 2);
                ldsm_x4(bh, uBh + boff);
#pragma unroll
                for (int i = 0; i < 2; i++) {
                    mma_f16(acc[i * 8 + 2 * jj],     ah[i], bh);
                    mma_f16(acc[i * 8 + 2 * jj + 1], ah[i], bh + 2);
                }
            }
        }
    }

    __syncthreads();
#pragma unroll
    for (int i = 0; i < 2; i++)
#pragma unroll
        for (int f = 0; f < 8; f++) {
            const int row = wr * 32 + i * 16 + g;
            const int col = wc * 64 + 8 * f + 2 * t;
            const float* c = acc[i * 8 + f];
            *(float2*)&Cs[row * 132 + col]       = make_float2(c[0], c[1]);
            *(float2*)&Cs[(row + 8) * 132 + col] = make_float2(c[2], c[3]);
        }
    __syncthreads();

    {
        const int r = tid >> 1;
        const int cb = (tid & 1) * 64;
        const float* bp = bias + n0 + cb;
        const float* sp = &Cs[r * 132 + cb];
        if (hilo == 0) {
            float* cp = Cf + (size_t)(m0 + r) * N + n0 + cb;
#pragma unroll
            for (int j = 0; j < 64; j += 4) {
                float4 o;
                o.x = sp[j+0] + bp[j+0]; o.y = sp[j+1] + bp[j+1];
                o.z = sp[j+2] + bp[j+2]; o.w = sp[j+3] + bp[j+3];
                *(float4*)(cp + j) = o;
            }
        } else {
            __half* hp = Ch + (size_t)(m0 + r) * N + n0 + cb;
#pragma unroll
            for (int j = 0; j < 64; j += 4) {
                uint32_t h0 = pack_h(sp[j+0] + bp[j+0], sp[j+1] + bp[j+1]);
                uint32_t h1 = pack_h(sp[j+2] + bp[j+2], sp[j+3] + bp[j+3]);
                *(uint2*)(hp + j) = make_uint2(h0, h1);
            }
        }
    }
}

// ---------------------------------------------------------------------------
// Flash attention fp16, 1-pass QK and PV; output rounded fp16.
// Now 2 CTAs/SM (92 KB smem each) for latency/imbalance hiding.
// ---------------------------------------------------------------------------
#define ALD 72                              // fp16 elems per smem row
#define FARR (128 * ALD * 2)                // 18432 B per array
#define FA_KVSTAGE (2 * FARR)               // Kh Vh = 36864 B
#define FA_KVBASE  FARR                     // after Qh
#define FA_SMEM (FA_KVBASE + 2 * FA_KVSTAGE)  // 92160 B

__global__ __launch_bounds__(256, 2)
void flash_attn_mma_kernel(const __half* __restrict__ qkv,
                           __half* __restrict__ oh)
{
    extern __shared__ char smraw[];
    __half* sQh = (__half*)smraw;
    const uint32_t sb = smem_u32(smraw);

    const int qb  = gridDim.x - 1 - blockIdx.x;   // long rows first
    const int h   = blockIdx.y;
    const int tid = threadIdx.x;
    const int wid = tid >> 5;
    const int lane = tid & 31;
    const int q0  = qb * 128;

    const int g  = lane >> 2;
    const int t  = lane & 3;
    const int lr = lane & 15;
    const int lc8 = (lane >> 4) * 8;
    const int kk = (lane & 7) + ((lane & 16) >> 1);
    const int kd8 = lane & 8;

    const int colK = D_MODEL + h * HEAD_DIM;
    const int colV = 2 * D_MODEL + h * HEAD_DIM;

    int crow[4], cbyte[4];
#pragma unroll
    for (int i = 0; i < 4; i++) {
        const int idx = tid + i * 256;
        crow[i]  = idx >> 3;
        cbyte[i] = (idx & 7) * 16;
    }

    // ---- load Q tile ----
#pragma unroll
    for (int i = 0; i < 4; i++) {
        const int r = crow[i], c = cbyte[i] / 2;
        const size_t gofs = (size_t)(q0 + r) * QKV_COLS + h * HEAD_DIM + c;
        *(uint4*)(sQh + r * ALD + c) = *(const uint4*)(qkv + gofs);
    }

    // ---- prefetch K/V stage 0 ----
    {
        const uint32_t st = sb + FA_KVBASE;
#pragma unroll
        for (int i = 0; i < 4; i++) {
            const int r = crow[i];
            const uint32_t so = (uint32_t)(r * ALD * 2 + cbyte[i]);
            const size_t gr = (size_t)r * QKV_COLS;
            const int c = cbyte[i] / 2;
            cp_async16(st + so,        qkv + gr + colK + c);
            cp_async16(st + FARR + so, qkv + gr + colV + c);
        }
        CP_COMMIT();
    }

    float ofr[8][4];
    float m0 = -1e30f, m1 = -1e30f, l0 = 0.f, l1 = 0.f;
#pragma unroll
    for (int j = 0; j < 8; j++)
#pragma unroll
        for (int e = 0; e < 4; e++) ofr[j][e] = 0.f;

    for (int kt = 0; kt <= qb; kt++) {
        __syncthreads();
        if (kt + 1 <= qb) {
            const int k1 = (kt + 1) * 128;
            const uint32_t st = sb + FA_KVBASE + ((kt + 1) & 1) * FA_KVSTAGE;
#pragma unroll
            for (int i = 0; i < 4; i++) {
                const int r = crow[i];
                const uint32_t so = (uint32_t)(r * ALD * 2 + cbyte[i]);
                const size_t gr = (size_t)(k1 + r) * QKV_COLS;
                const int c = cbyte[i] / 2;
                cp_async16(st + so,        qkv + gr + colK + c);
                cp_async16(st + FARR + so, qkv + gr + colV + c);
            }
            CP_COMMIT();
            CP_WAIT(1);
        } else {
            CP_WAIT(0);
        }
        __syncthreads();

        const uint32_t stg = sb + FA_KVBASE + (kt & 1) * FA_KVSTAGE;
        const uint32_t uKh = stg, uVh = stg + FARR;
        const uint32_t uQh = sb;

        // ---- S = Qh·Kh^T ----
        float sfr[16][4];
#pragma unroll
        for (int j = 0; j < 16; j++)
#pragma unroll
            for (int e = 0; e < 4; e++) sfr[j][e] = 0.f;

#pragma unroll
        for (int u = 0; u < 4; u++) {
            uint32_t aQh[4];
            const uint32_t qoff =
                (uint32_t)(((wid * 16 + lr) * ALD + 16 * u + lc8) * 2);
            ldsm_x4(aQh, uQh + qoff);
#pragma unroll
            for (int jj = 0; jj < 8; jj++) {
                uint32_t bKh[4];
                const uint32_t koff =
                    (uint32_t)(((16 * jj + kk) * ALD + 16 * u + kd8) * 2);
                ldsm_x4(bKh, uKh + koff);
                mma_f16(sfr[2*jj],   aQh, bKh);
                mma_f16(sfr[2*jj+1], aQh, bKh + 2);
            }
        }

        // ---- scale + causal mask ----
        if (kt == qb) {
            const int gq0 = wid * 16 + g, gq1 = gq0 + 8;
#pragma unroll
            for (int j = 0; j < 16; j++) {
                const int c = 8 * j + 2 * t;
                sfr[j][0] = (c     <= gq0) ? sfr[j][0] * ATT_SCALE : -1e30f;
                sfr[j][1] = (c + 1 <= gq0) ? sfr[j][1] * ATT_SCALE : -1e30f;
                sfr[j][2] = (c     <= gq1) ? sfr[j][2] * ATT_SCALE : -1e30f;
                sfr[j][3] = (c + 1 <= gq1) ? sfr[j][3] * ATT_SCALE : -1e30f;
            }
        } else {
#pragma unroll
            for (int j = 0; j < 16; j++) {
                sfr[j][0] *= ATT_SCALE; sfr[j][1] *= ATT_SCALE;
                sfr[j][2] *= ATT_SCALE; sfr[j][3] *= ATT_SCALE;
            }
        }

        // ---- online softmax ----
        float mn0 = m0, mn1 = m1;
#pragma unroll
        for (int j = 0; j < 16; j++) {
            mn0 = fmaxf(mn0, fmaxf(sfr[j][0], sfr[j][1]));
            mn1 = fmaxf(mn1, fmaxf(sfr[j][2], sfr[j][3]));
        }
        mn0 = fmaxf(mn0, __shfl_xor_sync(0xffffffffu, mn0, 1));
        mn0 = fmaxf(mn0, __shfl_xor_sync(0xffffffffu, mn0, 2));
        mn1 = fmaxf(mn1, __shfl_xor_sync(0xffffffffu, mn1, 1));
        mn1 = fmaxf(mn1, __shfl_xor_sync(0xffffffffu, mn1, 2));

        const float alpha0 = __expf(m0 - mn0);
        const float alpha1 = __expf(m1 - mn1);
        m0 = mn0; m1 = mn1;

        float sum0 = 0.f, sum1 = 0.f;
#pragma unroll
        for (int j = 0; j < 16; j++) {
            sfr[j][0] = __expf(sfr[j][0] - mn0);
            sfr[j][1] = __expf(sfr[j][1] - mn0);
            sfr[j][2] = __expf(sfr[j][2] - mn1);
            sfr[j][3] = __expf(sfr[j][3] - mn1);
            sum0 += sfr[j][0] + sfr[j][1];
            sum1 += sfr[j][2] + sfr[j][3];
        }
        sum0 += __shfl_xor_sync(0xffffffffu, sum0, 1);
        sum0 += __shfl_xor_sync(0xffffffffu, sum0, 2);
        sum1 += __shfl_xor_sync(0xffffffffu, sum1, 1);
        sum1 += __shfl_xor_sync(0xffffffffu, sum1, 2);
        l0 = l0 * alpha0 + sum0;
        l1 = l1 * alpha1 + sum1;

#pragma unroll
        for (int j = 0; j < 8; j++) {
            ofr[j][0] *= alpha0; ofr[j][1] *= alpha0;
            ofr[j][2] *= alpha1; ofr[j][3] *= alpha1;
        }

        // ---- O += Ph·Vh ----
#pragma unroll
        for (int u = 0; u < 8; u++) {
            uint32_t aPh[4];
            aPh[0] = pack_h(sfr[2*u][0],   sfr[2*u][1]);
            aPh[1] = pack_h(sfr[2*u][2],   sfr[2*u][3]);
            aPh[2] = pack_h(sfr[2*u+1][0], sfr[2*u+1][1]);
            aPh[3] = pack_h(sfr[2*u+1][2], sfr[2*u+1][3]);
#pragma unroll
            for (int cc = 0; cc < 4; cc++) {
                uint32_t bVh[4];
                const uint32_t voff =
                    (uint32_t)(((16 * u + lr) * ALD + 16 * cc + lc8) * 2);
                ldsm_x4_t(bVh, uVh + voff);
                mma_f16(ofr[2*cc],     aPh, bVh);
                mma_f16(ofr[2*cc + 1], aPh, bVh + 2);
            }
        }
    }

    // ---- epilogue: normalize, round fp16, store ----
    const float inv0 = 1.f / l0, inv1 = 1.f / l1;
    const int row0 = q0 + wid * 16 + g, row1 = row0 + 8;
#pragma unroll
    for (int j = 0; j < 8; j++) {
        const int c = h * HEAD_DIM + 8 * j + 2 * t;
        *(uint32_t*)(oh + (size_t)row0 * D_MODEL + c) =
            pack_h(ofr[j][0] * inv0, ofr[j][1] * inv0);
        *(uint32_t*)(oh + (size_t)row1 * D_MODEL + c) =
            pack_h(ofr[j][2] * inv1, ofr[j][3] * inv1);
    }
}

// ---------------------------------------------------------------------------
extern "C" void kernel_launch(void* const* d_in, const int* in_sizes, int n_in,
                              void* d_out, int out_size)
{
    const float* x     = (const float*)d_in[0];
    const float* w_qkv = (const float*)d_in[1];
    const float* b_qkv = (const float*)d_in[2];
    const float* w_out = (const float*)d_in[3];
    const float* b_out = (const float*)d_in[4];
    float* out = (float*)d_out;

    __half *xh, *qkv, *ah, *wqh, *woh;
    cudaGetSymbolAddress((void**)&xh, g_xh);
    cudaGetSymbolAddress((void**)&qkv, g_qkv);
    cudaGetSymbolAddress((void**)&ah, g_ah);
    cudaGetSymbolAddress((void**)&wqh, g_wqh);
    cudaGetSymbolAddress((void**)&woh, g_woh);

    cudaFuncSetAttribute(gemm_mma_kernel,
                         cudaFuncAttributeMaxDynamicSharedMemorySize, GEMM_SMEM);
    cudaFuncSetAttribute(flash_attn_mma_kernel,
                         cudaFuncAttributeMaxDynamicSharedMemorySize, FA_SMEM);

    {
        const int nx = S_LEN * D_MODEL;
        round_rows_kernel<<<nx / (256 * 4), 256>>>(x, xh, nx);
        dim3 g1(QKV_COLS / 32, D_MODEL / 32), b1(32, 8);
        transpose_round_kernel<<<g1, b1>>>(w_qkv, wqh, D_MODEL, QKV_COLS);
        dim3 g2(D_MODEL / 32, D_MODEL / 32);
        transpose_round_kernel<<<g2, b1>>>(w_out, woh, D_MODEL, D_MODEL);
    }

    // 1) qkv (fp16) = xh @ wqh + b_qkv   (1-pass)
    {
        dim3 grid(QKV_COLS / 128, S_LEN / 128);
        gemm_mma_kernel<<<grid, 256, GEMM_SMEM>>>(xh, wqh, b_qkv,
                                                  nullptr, qkv, 2,
                                                  S_LEN, QKV_COLS, D_MODEL);
    }
    // 2) attention -> ah (fp16, rounded)
    {
        dim3 grid(S_LEN / 128, N_HEADS);
        flash_attn_mma_kernel<<<grid, 256, FA_SMEM>>>(qkv, ah);
    }
    // 3) out = ah @ woh + b_out (fp32, 1-pass)
    {
        dim3 grid(D_MODEL / 128, S_LEN / 128);
        gemm_mma_kernel<<<grid, 256, GEMM_SMEM>>>(ah, woh, b_out,
                                                  out, nullptr, 0,
                                                  S_LEN, D_MODEL, D_MODEL);
    }
}